// round 2
// baseline (speedup 1.0000x reference)
#include <cuda_runtime.h>
#include <cuda_bf16.h>
#include <math.h>

// Problem constants
constexpr int LL   = 8192;
constexpr int NB   = 2;
constexpr int EE   = 256;
constexpr int HH   = 8;
constexpr int HD   = 32;          // head dim
constexpr int TAPS = 33;          // WINDOW//2 + 1
constexpr int M    = LL * NB;     // 16384 rows for all GEMMs
constexpr int LNE  = M * EE;      // 4,194,304 elements
constexpr float NEG = -1000000000.0f;

// Scratch (allocation-free: one device-global block, 4 x 16 MB slices)
__device__ float g_scratch[4 * LNE];

// ---------------------------------------------------------------------------
// GEMM: C[m, n] = sum_k A[m, k] * W[n, k] + bias[n]
// A: (M, 256) row-major.  W: rows are output features, K-contiguous (NT gemm).
// BM=128, BN=64, BK=16, 256 threads, 8x4 micro-tile per thread.
// ---------------------------------------------------------------------------
__global__ __launch_bounds__(256) void gemm_nt_bias(
    const float* __restrict__ A,
    const float* __restrict__ W,
    const float* __restrict__ bias,
    float* __restrict__ C)
{
    constexpr int BM = 128, BN = 64, BK = 16;
    __shared__ float As[BK][BM];
    __shared__ float Ws[BK][BN];

    const int tid = threadIdx.x;
    const int tx  = tid & 15;        // 0..15 -> 4 cols each
    const int ty  = tid >> 4;        // 0..15 -> 8 rows each
    const int m0  = blockIdx.y * BM;
    const int n0  = blockIdx.x * BN;

    float acc[8][4];
#pragma unroll
    for (int i = 0; i < 8; i++)
#pragma unroll
        for (int j = 0; j < 4; j++) acc[i][j] = 0.0f;

    const int lr  = tid >> 2;        // 0..63 : row within tile (loads)
    const int lc4 = tid & 3;         // 0..3  : which float4 along k

    for (int k0 = 0; k0 < EE; k0 += BK) {
        // A tile: 128 rows x 16 k -> 512 float4, 2 per thread
#pragma unroll
        for (int p = 0; p < 2; p++) {
            const int r = lr + p * 64;
            float4 a4 = *reinterpret_cast<const float4*>(
                &A[(size_t)(m0 + r) * EE + k0 + lc4 * 4]);
            As[lc4 * 4 + 0][r] = a4.x;
            As[lc4 * 4 + 1][r] = a4.y;
            As[lc4 * 4 + 2][r] = a4.z;
            As[lc4 * 4 + 3][r] = a4.w;
        }
        // W tile: 64 rows x 16 k -> 256 float4, 1 per thread
        {
            float4 w4 = *reinterpret_cast<const float4*>(
                &W[(size_t)(n0 + lr) * EE + k0 + lc4 * 4]);
            Ws[lc4 * 4 + 0][lr] = w4.x;
            Ws[lc4 * 4 + 1][lr] = w4.y;
            Ws[lc4 * 4 + 2][lr] = w4.z;
            Ws[lc4 * 4 + 3][lr] = w4.w;
        }
        __syncthreads();

#pragma unroll
        for (int kk = 0; kk < BK; kk++) {
            float a[8], b[4];
#pragma unroll
            for (int i = 0; i < 8; i++) a[i] = As[kk][ty * 8 + i];
#pragma unroll
            for (int j = 0; j < 4; j++) b[j] = Ws[kk][tx * 4 + j];
#pragma unroll
            for (int i = 0; i < 8; i++)
#pragma unroll
                for (int j = 0; j < 4; j++) acc[i][j] += a[i] * b[j];
        }
        __syncthreads();
    }

    const float4 b4 = *reinterpret_cast<const float4*>(&bias[n0 + tx * 4]);
#pragma unroll
    for (int i = 0; i < 8; i++) {
        float4 o;
        o.x = acc[i][0] + b4.x;
        o.y = acc[i][1] + b4.y;
        o.z = acc[i][2] + b4.z;
        o.w = acc[i][3] + b4.w;
        *reinterpret_cast<float4*>(
            &C[(size_t)(m0 + ty * 8 + i) * EE + n0 + tx * 4]) = o;
    }
}

// ---------------------------------------------------------------------------
// Sliding-window causal attention.
// Block: 256 threads (8 warps) handles TL=64 query positions for one (n, h).
// k/v rows [l0-32, l0+63] staged into smem (96 rows x 32 floats each).
// Each warp handles 8 queries; lane = head-dim element; dots via shfl-xor.
// ---------------------------------------------------------------------------
constexpr int TL = 64;

__global__ __launch_bounds__(256) void attn_window(
    const float* __restrict__ q,
    const float* __restrict__ k,
    const float* __restrict__ v,
    float* __restrict__ o)
{
    __shared__ float ks[TL + 32][HD];
    __shared__ float vs[TL + 32][HD];

    const int nh   = blockIdx.y;           // 0..15
    const int n    = nh / HH;
    const int h    = nh % HH;
    const int l0   = blockIdx.x * TL;
    const int tid  = threadIdx.x;
    const int lane = tid & 31;
    const int wid  = tid >> 5;

    // Stage k/v: rows r=0..95 correspond to global l = l0 - 32 + r.
    for (int r = wid; r < TL + 32; r += 8) {
        const int gl = l0 - 32 + r;
        float kv = 0.0f, vv = 0.0f;
        if (gl >= 0) {
            const size_t base = ((size_t)gl * NB + n) * EE + h * HD + lane;
            kv = k[base];
            vv = v[base];
        }
        ks[r][lane] = kv;
        vs[r][lane] = vv;
    }
    __syncthreads();

    const float scale = 0.17677669529663687f;  // 1/sqrt(32)

#pragma unroll 1
    for (int ii = 0; ii < 8; ii++) {
        const int l  = l0 + wid * 8 + ii;
        const int li = l - l0 + 32;            // smem row of key at offset 0
        const size_t qbase = ((size_t)l * NB + n) * EE + h * HD + lane;
        const float qd = q[qbase] * scale;

        float s[TAPS];
#pragma unroll
        for (int w = 0; w < TAPS; w++) {
            float prod = (w <= l) ? qd * ks[li - w][lane] : 0.0f;
#pragma unroll
            for (int off = 16; off > 0; off >>= 1)
                prod += __shfl_xor_sync(0xFFFFFFFFu, prod, off);
            s[w] = (w <= l) ? prod : NEG;
        }

        float mx = s[0];
#pragma unroll
        for (int w = 1; w < TAPS; w++) mx = fmaxf(mx, s[w]);
        float den = 0.0f;
#pragma unroll
        for (int w = 0; w < TAPS; w++) {
            const float e = __expf(s[w] - mx);
            s[w] = e;
            den += e;
        }
        const float inv = 1.0f / den;

        float out = 0.0f;
#pragma unroll
        for (int w = 0; w < TAPS; w++) out += s[w] * vs[li - w][lane];

        o[qbase] = out * inv;
    }
}

// ---------------------------------------------------------------------------
extern "C" void kernel_launch(void* const* d_in, const int* in_sizes, int n_in,
                              void* d_out, int out_size)
{
    const float* query = (const float*)d_in[0];
    const float* key   = (const float*)d_in[1];
    const float* value = (const float*)d_in[2];
    const float* w_in  = (const float*)d_in[3];   // (768, 256)
    const float* b_in  = (const float*)d_in[4];   // (768,)
    const float* w_out = (const float*)d_in[5];   // (256, 256)
    const float* b_out = (const float*)d_in[6];   // (256,)
    float* out = (float*)d_out;

    float* base = nullptr;
    cudaGetSymbolAddress((void**)&base, g_scratch);
    float* gq = base + 0 * LNE;
    float* gk = base + 1 * LNE;
    float* gv = base + 2 * LNE;
    float* go = base + 3 * LNE;

    dim3 ggrid(EE / 64, M / 128);   // (4, 128)

    gemm_nt_bias<<<ggrid, 256>>>(query, w_in,               b_in,          gq);
    gemm_nt_bias<<<ggrid, 256>>>(key,   w_in + EE * EE,     b_in + EE,     gk);
    gemm_nt_bias<<<ggrid, 256>>>(value, w_in + 2 * EE * EE, b_in + 2 * EE, gv);

    attn_window<<<dim3(LL / TL, NB * HH), 256>>>(gq, gk, gv, go);

    gemm_nt_bias<<<ggrid, 256>>>(go, w_out, b_out, out);
}

// round 3
// speedup vs baseline: 1.1658x; 1.1658x over previous
#include <cuda_runtime.h>
#include <cuda_bf16.h>
#include <math.h>
#include <stdint.h>

// Problem constants
constexpr int LL   = 8192;
constexpr int NB   = 2;
constexpr int EE   = 256;
constexpr int HH   = 8;
constexpr int HD   = 32;
constexpr int TAPS = 33;
constexpr int M    = LL * NB;     // 16384
constexpr int LNE  = M * EE;
constexpr float NEG = -1000000000.0f;

__device__ float g_scratch[4 * LNE];

// ---------------------------------------------------------------------------
// tf32 helpers
// ---------------------------------------------------------------------------
__device__ __forceinline__ uint32_t f2tf32(float x) {
    uint32_t r;
    asm("cvt.rna.tf32.f32 %0, %1;" : "=r"(r) : "f"(x));
    return r;
}

__device__ __forceinline__ void mma_tf32(float* c,
    uint32_t a0, uint32_t a1, uint32_t a2, uint32_t a3,
    uint32_t b0, uint32_t b1)
{
    asm volatile(
        "mma.sync.aligned.m16n8k8.row.col.f32.tf32.tf32.f32 "
        "{%0,%1,%2,%3}, {%4,%5,%6,%7}, {%8,%9}, {%0,%1,%2,%3};"
        : "+f"(c[0]), "+f"(c[1]), "+f"(c[2]), "+f"(c[3])
        : "r"(a0), "r"(a1), "r"(a2), "r"(a3), "r"(b0), "r"(b1));
}

// ---------------------------------------------------------------------------
// GEMM via tf32 tensor cores with hi/lo error compensation (3 MMAs).
// C[m,n] = sum_k A[m,k] * W[n,k] + bias[n].
// BM=128, BN=64, BK=16. 256 threads = 8 warps (4 m x 2 n), warp tile 32x32.
// ---------------------------------------------------------------------------
constexpr int BM = 128, BN = 64, BK = 16, LDT = BK + 4;  // stride 20: conflict-free frags

__global__ __launch_bounds__(256) void gemm_tf32(
    const float* __restrict__ A,
    const float* __restrict__ W,
    const float* __restrict__ bias,
    float* __restrict__ C)
{
    __shared__ float Ah[BM][LDT], Al[BM][LDT];
    __shared__ float Bh[BN][LDT], Bl[BN][LDT];

    const int tid  = threadIdx.x;
    const int lane = tid & 31;
    const int wid  = tid >> 5;
    const int wm   = wid & 3;        // 0..3
    const int wn   = wid >> 2;       // 0..1
    const int grp  = lane >> 2;      // 0..7
    const int tig  = lane & 3;       // 0..3
    const int m0   = blockIdx.y * BM;
    const int n0   = blockIdx.x * BN;

    float acc[2][4][4];
#pragma unroll
    for (int mt = 0; mt < 2; mt++)
#pragma unroll
        for (int nt = 0; nt < 4; nt++)
#pragma unroll
            for (int i = 0; i < 4; i++) acc[mt][nt][i] = 0.0f;

    for (int k0 = 0; k0 < EE; k0 += BK) {
        // Stage A tile (128 x 16): 512 float4, 2 per thread; convert to hi/lo.
#pragma unroll
        for (int p = 0; p < 2; p++) {
            const int f   = tid + p * 256;
            const int row = f >> 2;
            const int kc  = (f & 3) * 4;
            float4 a4 = *reinterpret_cast<const float4*>(
                &A[(size_t)(m0 + row) * EE + k0 + kc]);
            float v[4] = {a4.x, a4.y, a4.z, a4.w};
#pragma unroll
            for (int i = 0; i < 4; i++) {
                uint32_t h = f2tf32(v[i]);
                float hf = __uint_as_float(h);
                uint32_t l = f2tf32(v[i] - hf);
                Ah[row][kc + i] = hf;
                Al[row][kc + i] = __uint_as_float(l);
            }
        }
        // Stage W tile (64 x 16): 256 float4, 1 per thread.
        {
            const int row = tid >> 2;
            const int kc  = (tid & 3) * 4;
            float4 w4 = *reinterpret_cast<const float4*>(
                &W[(size_t)(n0 + row) * EE + k0 + kc]);
            float v[4] = {w4.x, w4.y, w4.z, w4.w};
#pragma unroll
            for (int i = 0; i < 4; i++) {
                uint32_t h = f2tf32(v[i]);
                float hf = __uint_as_float(h);
                uint32_t l = f2tf32(v[i] - hf);
                Bh[row][kc + i] = hf;
                Bl[row][kc + i] = __uint_as_float(l);
            }
        }
        __syncthreads();

#pragma unroll
        for (int kk = 0; kk < BK; kk += 8) {
            uint32_t ah[2][4], al[2][4];
#pragma unroll
            for (int mt = 0; mt < 2; mt++) {
                const int r0 = wm * 32 + mt * 16 + grp;
                ah[mt][0] = __float_as_uint(Ah[r0    ][kk + tig]);
                ah[mt][1] = __float_as_uint(Ah[r0 + 8][kk + tig]);
                ah[mt][2] = __float_as_uint(Ah[r0    ][kk + tig + 4]);
                ah[mt][3] = __float_as_uint(Ah[r0 + 8][kk + tig + 4]);
                al[mt][0] = __float_as_uint(Al[r0    ][kk + tig]);
                al[mt][1] = __float_as_uint(Al[r0 + 8][kk + tig]);
                al[mt][2] = __float_as_uint(Al[r0    ][kk + tig + 4]);
                al[mt][3] = __float_as_uint(Al[r0 + 8][kk + tig + 4]);
            }
#pragma unroll
            for (int nt = 0; nt < 4; nt++) {
                const int nr = wn * 32 + nt * 8 + grp;
                const uint32_t bh0 = __float_as_uint(Bh[nr][kk + tig]);
                const uint32_t bh1 = __float_as_uint(Bh[nr][kk + tig + 4]);
                const uint32_t bl0 = __float_as_uint(Bl[nr][kk + tig]);
                const uint32_t bl1 = __float_as_uint(Bl[nr][kk + tig + 4]);
#pragma unroll
                for (int mt = 0; mt < 2; mt++) {
                    mma_tf32(acc[mt][nt], ah[mt][0], ah[mt][1], ah[mt][2], ah[mt][3], bh0, bh1);
                    mma_tf32(acc[mt][nt], ah[mt][0], ah[mt][1], ah[mt][2], ah[mt][3], bl0, bl1);
                    mma_tf32(acc[mt][nt], al[mt][0], al[mt][1], al[mt][2], al[mt][3], bh0, bh1);
                }
            }
        }
        __syncthreads();
    }

    // Epilogue: bias + store (float2 per c-pair).
#pragma unroll
    for (int mt = 0; mt < 2; mt++) {
        const int r0 = m0 + wm * 32 + mt * 16 + grp;
#pragma unroll
        for (int nt = 0; nt < 4; nt++) {
            const int c = n0 + wn * 32 + nt * 8 + 2 * tig;
            const float b0v = bias[c], b1v = bias[c + 1];
            float2 o0 = make_float2(acc[mt][nt][0] + b0v, acc[mt][nt][1] + b1v);
            float2 o1 = make_float2(acc[mt][nt][2] + b0v, acc[mt][nt][3] + b1v);
            *reinterpret_cast<float2*>(&C[(size_t)r0 * EE + c]) = o0;
            *reinterpret_cast<float2*>(&C[(size_t)(r0 + 8) * EE + c]) = o1;
        }
    }
}

// ---------------------------------------------------------------------------
// Sliding-window attention, lane = tap layout.
// Block: 256 thr / 8 warps, 64 queries per block for one (n, h).
// Warp handles 8 queries sequentially; per query:
//   - lanes 0..31 compute score for taps 0..31 via d-loop (conflict-free smem)
//   - tap 32 via one 5-shfl reduction
//   - softmax: ONE exp per lane + warp max/sum reductions
//   - output: lane = dim, attn broadcast by shfl
// ---------------------------------------------------------------------------
constexpr int TL = 64;
constexpr int KROWS = TL + 32;   // 96

__global__ __launch_bounds__(256) void attn_window(
    const float* __restrict__ q,
    const float* __restrict__ k,
    const float* __restrict__ v,
    float* __restrict__ o)
{
    __shared__ float ks[KROWS][HD + 1];   // stride 33: bank = (row + d) % 32
    __shared__ float vs[KROWS][HD + 1];
    __shared__ float qs[TL][HD + 1];

    const int nh   = blockIdx.y;
    const int n    = nh / HH;
    const int h    = nh % HH;
    const int l0   = blockIdx.x * TL;
    const int tid  = threadIdx.x;
    const int lane = tid & 31;
    const int wid  = tid >> 5;

    const float scale = 0.17677669529663687f;  // 1/sqrt(32)

    // Stage k/v rows [l0-32, l0+63]
#pragma unroll
    for (int i = 0; i < KROWS / 8; i++) {
        const int r  = wid + i * 8;
        const int gl = l0 - 32 + r;
        float kv = 0.0f, vv = 0.0f;
        if (gl >= 0) {
            const size_t base = ((size_t)gl * NB + n) * EE + h * HD + lane;
            kv = k[base];
            vv = v[base];
        }
        ks[r][lane] = kv;
        vs[r][lane] = vv;
    }
    // Stage q rows (pre-scaled)
#pragma unroll
    for (int i = 0; i < TL / 8; i++) {
        const int r = wid + i * 8;
        qs[r][lane] = q[((size_t)(l0 + r) * NB + n) * EE + h * HD + lane] * scale;
    }
    __syncthreads();

#pragma unroll 1
    for (int ii = 0; ii < 8; ii++) {
        const int qr = wid * 8 + ii;          // query row in tile
        const int l  = l0 + qr;               // global query index
        const int li = qr + 32;               // smem row of key at tap 0

        // --- scores: lane t handles tap t
        float s = 0.0f;
        const int kr = li - lane;             // smem row for this lane's tap
#pragma unroll
        for (int d = 0; d < HD; d++)
            s += qs[qr][d] * ks[kr][d];
        if (lane > l) s = NEG;                // causal mask (only block 0)

        // --- tap 32 via warp reduction
        float p32 = qs[qr][lane] * ks[li - 32][lane];
#pragma unroll
        for (int off = 16; off > 0; off >>= 1)
            p32 += __shfl_xor_sync(0xFFFFFFFFu, p32, off);
        const float s32 = (l >= 32) ? p32 : NEG;

        // --- softmax over 33 values (32 in lanes + s32 known to all)
        float mx = s;
#pragma unroll
        for (int off = 16; off > 0; off >>= 1)
            mx = fmaxf(mx, __shfl_xor_sync(0xFFFFFFFFu, mx, off));
        mx = fmaxf(mx, s32);

        const float e   = __expf(s - mx);
        const float e32 = __expf(s32 - mx);

        float den = e;
#pragma unroll
        for (int off = 16; off > 0; off >>= 1)
            den += __shfl_xor_sync(0xFFFFFFFFu, den, off);
        den += e32;
        const float inv = 1.0f / den;

        // --- output: lane = dim d
        float acc = e32 * vs[li - 32][lane];
#pragma unroll
        for (int w = 0; w < 32; w++) {
            const float ew = __shfl_sync(0xFFFFFFFFu, e, w);
            acc += ew * vs[li - w][lane];
        }

        o[((size_t)l * NB + n) * EE + h * HD + lane] = acc * inv;
    }
}

// ---------------------------------------------------------------------------
extern "C" void kernel_launch(void* const* d_in, const int* in_sizes, int n_in,
                              void* d_out, int out_size)
{
    const float* query = (const float*)d_in[0];
    const float* key   = (const float*)d_in[1];
    const float* value = (const float*)d_in[2];
    const float* w_in  = (const float*)d_in[3];   // (768, 256)
    const float* b_in  = (const float*)d_in[4];   // (768,)
    const float* w_out = (const float*)d_in[5];   // (256, 256)
    const float* b_out = (const float*)d_in[6];   // (256,)
    float* out = (float*)d_out;

    float* base = nullptr;
    cudaGetSymbolAddress((void**)&base, g_scratch);
    float* gq = base + 0 * LNE;
    float* gk = base + 1 * LNE;
    float* gv = base + 2 * LNE;
    float* go = base + 3 * LNE;

    dim3 ggrid(EE / BN, M / BM);   // (4, 128)

    gemm_tf32<<<ggrid, 256>>>(query, w_in,               b_in,          gq);
    gemm_tf32<<<ggrid, 256>>>(key,   w_in + EE * EE,     b_in + EE,     gk);
    gemm_tf32<<<ggrid, 256>>>(value, w_in + 2 * EE * EE, b_in + 2 * EE, gv);

    attn_window<<<dim3(LL / TL, NB * HH), 256>>>(gq, gk, gv, go);

    gemm_tf32<<<ggrid, 256>>>(go, w_out, b_out, out);
}

// round 5
// speedup vs baseline: 1.8392x; 1.5776x over previous
#include <cuda_runtime.h>
#include <cuda_bf16.h>
#include <math.h>
#include <stdint.h>

// Problem constants
constexpr int LL   = 8192;
constexpr int NB   = 2;
constexpr int EE   = 256;
constexpr int HH   = 8;
constexpr int HD   = 32;
constexpr int M    = LL * NB;     // 16384
constexpr int LNE  = M * EE;
constexpr float NEG = -1000000000.0f;

__device__ float g_scratch[4 * LNE];

// ---------------------------------------------------------------------------
// mma.sync bf16 m16n8k16 + ldmatrix helpers (compute_100-safe, sm_90 features)
// ---------------------------------------------------------------------------
__device__ __forceinline__ void mma_bf16(float* c,
    uint32_t a0, uint32_t a1, uint32_t a2, uint32_t a3,
    uint32_t b0, uint32_t b1)
{
    asm volatile(
        "mma.sync.aligned.m16n8k16.row.col.f32.bf16.bf16.f32 "
        "{%0,%1,%2,%3}, {%4,%5,%6,%7}, {%8,%9}, {%0,%1,%2,%3};"
        : "+f"(c[0]), "+f"(c[1]), "+f"(c[2]), "+f"(c[3])
        : "r"(a0), "r"(a1), "r"(a2), "r"(a3), "r"(b0), "r"(b1));
}

__device__ __forceinline__ void ldmx4(uint32_t* r, uint32_t addr) {
    asm volatile("ldmatrix.sync.aligned.m8n8.x4.shared.b16 {%0,%1,%2,%3}, [%4];"
        : "=r"(r[0]), "=r"(r[1]), "=r"(r[2]), "=r"(r[3]) : "r"(addr));
}

__device__ __forceinline__ uint32_t smem_u32(const void* p) {
    uint32_t a;
    asm("{ .reg .u64 t; cvta.to.shared.u64 t, %1; cvt.u32.u64 %0, t; }"
        : "=r"(a) : "l"(p));
    return a;
}

__device__ __forceinline__ void cvt_hilo(float x, __nv_bfloat16& h, __nv_bfloat16& l) {
    h = __float2bfloat16_rn(x);
    l = __float2bfloat16_rn(x - __bfloat162float(h));
}

// ---------------------------------------------------------------------------
// GEMM: C[m,n] = sum_k A[m,k] * W[n,k] + bias[n]
// bf16 hi/lo 3-term compensated, mma.m16n8k16, ldmatrix fragment feeds.
// BM=128, BN=64, BK=32. 256 threads = 8 warps (4 m x 2 n), warp tile 32x32.
// smem stride 40 bf16 (80 B): conflict-free ldmatrix phases.
// ---------------------------------------------------------------------------
constexpr int BM = 128, BN = 64, BK = 32, LDS_ = BK + 8;  // 40

__global__ __launch_bounds__(256) void gemm_bf16(
    const float* __restrict__ A,
    const float* __restrict__ W,
    const float* __restrict__ bias,
    float* __restrict__ C)
{
    __shared__ __nv_bfloat16 Ah[BM][LDS_], Al[BM][LDS_];
    __shared__ __nv_bfloat16 Bh[BN][LDS_], Bl[BN][LDS_];

    const int tid  = threadIdx.x;
    const int lane = tid & 31;
    const int wid  = tid >> 5;
    const int wm   = wid & 3;        // 0..3
    const int wn   = wid >> 2;       // 0..1
    const int grp  = lane >> 2;      // 0..7
    const int tig  = lane & 3;       // 0..3
    const int m0   = blockIdx.y * BM;
    const int n0   = blockIdx.x * BN;

    float acc[2][4][4];
#pragma unroll
    for (int mt = 0; mt < 2; mt++)
#pragma unroll
        for (int nt = 0; nt < 4; nt++)
#pragma unroll
            for (int i = 0; i < 4; i++) acc[mt][nt][i] = 0.0f;

    // ldmatrix lane->address mapping (element offsets within tile)
    // A: row = warp_row_base + (lane & 15), col = kbase + (lane >> 4) * 8
    const int a_row_l = lane & 15;
    const int a_col_l = (lane >> 4) * 8;
    // B: row = nb + (lane & 7) + (lane >= 16 ? 8 : 0), col = kbase + ((lane >> 3) & 1) * 8
    const int b_row_l = (lane & 7) + ((lane >> 4) << 3);
    const int b_col_l = ((lane >> 3) & 1) * 8;

    const uint32_t sAh = smem_u32(&Ah[0][0]);
    const uint32_t sAl = smem_u32(&Al[0][0]);
    const uint32_t sBh = smem_u32(&Bh[0][0]);
    const uint32_t sBl = smem_u32(&Bl[0][0]);

    for (int k0 = 0; k0 < EE; k0 += BK) {
        // Stage A tile (128 x 32): 1024 float4, 4 per thread
#pragma unroll
        for (int p = 0; p < 4; p++) {
            const int f   = tid + p * 256;
            const int row = f >> 3;
            const int kc  = (f & 7) * 4;
            float4 a4 = *reinterpret_cast<const float4*>(
                &A[(size_t)(m0 + row) * EE + k0 + kc]);
            __nv_bfloat16 h[4], l[4];
            cvt_hilo(a4.x, h[0], l[0]);
            cvt_hilo(a4.y, h[1], l[1]);
            cvt_hilo(a4.z, h[2], l[2]);
            cvt_hilo(a4.w, h[3], l[3]);
            *reinterpret_cast<uint2*>(&Ah[row][kc]) = *reinterpret_cast<uint2*>(h);
            *reinterpret_cast<uint2*>(&Al[row][kc]) = *reinterpret_cast<uint2*>(l);
        }
        // Stage W tile (64 x 32): 512 float4, 2 per thread
#pragma unroll
        for (int p = 0; p < 2; p++) {
            const int f   = tid + p * 256;
            const int row = f >> 3;
            const int kc  = (f & 7) * 4;
            float4 w4 = *reinterpret_cast<const float4*>(
                &W[(size_t)(n0 + row) * EE + k0 + kc]);
            __nv_bfloat16 h[4], l[4];
            cvt_hilo(w4.x, h[0], l[0]);
            cvt_hilo(w4.y, h[1], l[1]);
            cvt_hilo(w4.z, h[2], l[2]);
            cvt_hilo(w4.w, h[3], l[3]);
            *reinterpret_cast<uint2*>(&Bh[row][kc]) = *reinterpret_cast<uint2*>(h);
            *reinterpret_cast<uint2*>(&Bl[row][kc]) = *reinterpret_cast<uint2*>(l);
        }
        __syncthreads();

#pragma unroll
        for (int ks = 0; ks < 2; ks++) {
            const int kb = ks * 16;
            uint32_t ah[2][4], al[2][4];
#pragma unroll
            for (int mt = 0; mt < 2; mt++) {
                const uint32_t aoff =
                    ((wm * 32 + mt * 16 + a_row_l) * LDS_ + kb + a_col_l) * 2;
                ldmx4(ah[mt], sAh + aoff);
                ldmx4(al[mt], sAl + aoff);
            }
#pragma unroll
            for (int ntp = 0; ntp < 2; ntp++) {
                const uint32_t boff =
                    ((wn * 32 + ntp * 16 + b_row_l) * LDS_ + kb + b_col_l) * 2;
                uint32_t bh[4], bl[4];
                ldmx4(bh, sBh + boff);
                ldmx4(bl, sBl + boff);
#pragma unroll
                for (int j = 0; j < 2; j++) {
                    const int nt = ntp * 2 + j;
                    const uint32_t b0h = bh[2 * j], b1h = bh[2 * j + 1];
                    const uint32_t b0l = bl[2 * j], b1l = bl[2 * j + 1];
#pragma unroll
                    for (int mt = 0; mt < 2; mt++) {
                        mma_bf16(acc[mt][nt], ah[mt][0], ah[mt][1], ah[mt][2], ah[mt][3], b0h, b1h);
                        mma_bf16(acc[mt][nt], ah[mt][0], ah[mt][1], ah[mt][2], ah[mt][3], b0l, b1l);
                        mma_bf16(acc[mt][nt], al[mt][0], al[mt][1], al[mt][2], al[mt][3], b0h, b1h);
                    }
                }
            }
        }
        __syncthreads();
    }

    // Epilogue: bias + float2 stores
#pragma unroll
    for (int mt = 0; mt < 2; mt++) {
        const int r0 = m0 + wm * 32 + mt * 16 + grp;
#pragma unroll
        for (int nt = 0; nt < 4; nt++) {
            const int c = n0 + wn * 32 + nt * 8 + 2 * tig;
            const float b0v = bias[c], b1v = bias[c + 1];
            float2 o0 = make_float2(acc[mt][nt][0] + b0v, acc[mt][nt][1] + b1v);
            float2 o1 = make_float2(acc[mt][nt][2] + b0v, acc[mt][nt][3] + b1v);
            *reinterpret_cast<float2*>(&C[(size_t)r0 * EE + c]) = o0;
            *reinterpret_cast<float2*>(&C[(size_t)(r0 + 8) * EE + c]) = o1;
        }
    }
}

// ---------------------------------------------------------------------------
// Sliding-window attention (unchanged from Round 3: 83.2 us measured)
// ---------------------------------------------------------------------------
constexpr int TL = 64;
constexpr int KROWS = TL + 32;   // 96

__global__ __launch_bounds__(256) void attn_window(
    const float* __restrict__ q,
    const float* __restrict__ k,
    const float* __restrict__ v,
    float* __restrict__ o)
{
    __shared__ float ks[KROWS][HD + 1];
    __shared__ float vs[KROWS][HD + 1];
    __shared__ float qs[TL][HD + 1];

    const int nh   = blockIdx.y;
    const int n    = nh / HH;
    const int h    = nh % HH;
    const int l0   = blockIdx.x * TL;
    const int tid  = threadIdx.x;
    const int lane = tid & 31;
    const int wid  = tid >> 5;

    const float scale = 0.17677669529663687f;  // 1/sqrt(32)

#pragma unroll
    for (int i = 0; i < KROWS / 8; i++) {
        const int r  = wid + i * 8;
        const int gl = l0 - 32 + r;
        float kv = 0.0f, vv = 0.0f;
        if (gl >= 0) {
            const size_t base = ((size_t)gl * NB + n) * EE + h * HD + lane;
            kv = k[base];
            vv = v[base];
        }
        ks[r][lane] = kv;
        vs[r][lane] = vv;
    }
#pragma unroll
    for (int i = 0; i < TL / 8; i++) {
        const int r = wid + i * 8;
        qs[r][lane] = q[((size_t)(l0 + r) * NB + n) * EE + h * HD + lane] * scale;
    }
    __syncthreads();

#pragma unroll 1
    for (int ii = 0; ii < 8; ii++) {
        const int qr = wid * 8 + ii;
        const int l  = l0 + qr;
        const int li = qr + 32;

        float s = 0.0f;
        const int kr = li - lane;
#pragma unroll
        for (int d = 0; d < HD; d++)
            s += qs[qr][d] * ks[kr][d];
        if (lane > l) s = NEG;

        float p32 = qs[qr][lane] * ks[li - 32][lane];
#pragma unroll
        for (int off = 16; off > 0; off >>= 1)
            p32 += __shfl_xor_sync(0xFFFFFFFFu, p32, off);
        const float s32 = (l >= 32) ? p32 : NEG;

        float mx = s;
#pragma unroll
        for (int off = 16; off > 0; off >>= 1)
            mx = fmaxf(mx, __shfl_xor_sync(0xFFFFFFFFu, mx, off));
        mx = fmaxf(mx, s32);

        const float e   = __expf(s - mx);
        const float e32 = __expf(s32 - mx);

        float den = e;
#pragma unroll
        for (int off = 16; off > 0; off >>= 1)
            den += __shfl_xor_sync(0xFFFFFFFFu, den, off);
        den += e32;
        const float inv = 1.0f / den;

        float acc = e32 * vs[li - 32][lane];
#pragma unroll
        for (int w = 0; w < 32; w++) {
            const float ew = __shfl_sync(0xFFFFFFFFu, e, w);
            acc += ew * vs[li - w][lane];
        }

        o[((size_t)l * NB + n) * EE + h * HD + lane] = acc * inv;
    }
}

// ---------------------------------------------------------------------------
extern "C" void kernel_launch(void* const* d_in, const int* in_sizes, int n_in,
                              void* d_out, int out_size)
{
    const float* query = (const float*)d_in[0];
    const float* key   = (const float*)d_in[1];
    const float* value = (const float*)d_in[2];
    const float* w_in  = (const float*)d_in[3];
    const float* b_in  = (const float*)d_in[4];
    const float* w_out = (const float*)d_in[5];
    const float* b_out = (const float*)d_in[6];
    float* out = (float*)d_out;

    float* base = nullptr;
    cudaGetSymbolAddress((void**)&base, g_scratch);
    float* gq = base + 0 * LNE;
    float* gk = base + 1 * LNE;
    float* gv = base + 2 * LNE;
    float* go = base + 3 * LNE;

    dim3 ggrid(EE / BN, M / BM);   // (4, 128)

    gemm_bf16<<<ggrid, 256>>>(query, w_in,               b_in,          gq);
    gemm_bf16<<<ggrid, 256>>>(key,   w_in + EE * EE,     b_in + EE,     gk);
    gemm_bf16<<<ggrid, 256>>>(value, w_in + 2 * EE * EE, b_in + 2 * EE, gv);

    attn_window<<<dim3(LL / TL, NB * HH), 256>>>(gq, gk, gv, go);

    gemm_bf16<<<ggrid, 256>>>(go, w_out, b_out, out);
}

// round 7
// speedup vs baseline: 1.8607x; 1.0117x over previous
#include <cuda_runtime.h>
#include <cuda_bf16.h>
#include <math.h>
#include <stdint.h>

// Problem constants
constexpr int LL   = 8192;
constexpr int NB   = 2;
constexpr int EE   = 256;
constexpr int HH   = 8;
constexpr int HD   = 32;
constexpr int M    = LL * NB;     // 16384
constexpr int LNE  = M * EE;
constexpr int WELEMS = 768 * 256 + 256 * 256;  // 262144
constexpr float NEG = -1000000000.0f;

// Scratch: fp32 q/k/v after projection; bf16 hi/lo planes for GEMM inputs.
__device__ float         g_f32[3 * LNE];      // gq, gk, gv (fp32 for attention)
__device__ __nv_bfloat16 g_hi[4 * LNE];       // query,key,value,attn-out hi
__device__ __nv_bfloat16 g_lo[4 * LNE];       // lo planes
__device__ __nv_bfloat16 g_wh[WELEMS];        // w_in | w_out hi
__device__ __nv_bfloat16 g_wl[WELEMS];        // lo

// ---------------------------------------------------------------------------
__device__ __forceinline__ void mma_bf16(float* c,
    uint32_t a0, uint32_t a1, uint32_t a2, uint32_t a3,
    uint32_t b0, uint32_t b1)
{
    asm volatile(
        "mma.sync.aligned.m16n8k16.row.col.f32.bf16.bf16.f32 "
        "{%0,%1,%2,%3}, {%4,%5,%6,%7}, {%8,%9}, {%0,%1,%2,%3};"
        : "+f"(c[0]), "+f"(c[1]), "+f"(c[2]), "+f"(c[3])
        : "r"(a0), "r"(a1), "r"(a2), "r"(a3), "r"(b0), "r"(b1));
}

__device__ __forceinline__ void ldmx4(uint32_t* r, uint32_t addr) {
    asm volatile("ldmatrix.sync.aligned.m8n8.x4.shared.b16 {%0,%1,%2,%3}, [%4];"
        : "=r"(r[0]), "=r"(r[1]), "=r"(r[2]), "=r"(r[3]) : "r"(addr));
}

__device__ __forceinline__ uint32_t smem_u32(const void* p) {
    uint32_t a;
    asm("{ .reg .u64 t; cvta.to.shared.u64 t, %1; cvt.u32.u64 %0, t; }"
        : "=r"(a) : "l"(p));
    return a;
}

__device__ __forceinline__ void cvt_hilo(float x, __nv_bfloat16& h, __nv_bfloat16& l) {
    h = __float2bfloat16_rn(x);
    l = __float2bfloat16_rn(x - __bfloat162float(h));
}

// ---------------------------------------------------------------------------
// fp32 -> (hi, lo) bf16 planes, float4-granular.
// ---------------------------------------------------------------------------
__global__ __launch_bounds__(256) void cvt_planes(
    const float* __restrict__ x,
    __nv_bfloat16* __restrict__ hp,
    __nv_bfloat16* __restrict__ lp,
    int n4)
{
    const int i = blockIdx.x * 256 + threadIdx.x;
    if (i >= n4) return;
    float4 v = reinterpret_cast<const float4*>(x)[i];
    __nv_bfloat16 h[4], l[4];
    cvt_hilo(v.x, h[0], l[0]);
    cvt_hilo(v.y, h[1], l[1]);
    cvt_hilo(v.z, h[2], l[2]);
    cvt_hilo(v.w, h[3], l[3]);
    reinterpret_cast<uint2*>(hp)[i] = *reinterpret_cast<uint2*>(h);
    reinterpret_cast<uint2*>(lp)[i] = *reinterpret_cast<uint2*>(l);
}

// ---------------------------------------------------------------------------
// GEMM: C[m,n] = sum_k A[m,k]*W[n,k] + bias[n], pre-converted bf16 hi/lo inputs.
// BM=128, BN=64, BK=32. 256 threads = 8 warps (4m x 2n), warp tile 32x32.
// smem stride 40 bf16 (80 B): conflict-free ldmatrix phases.
// ---------------------------------------------------------------------------
constexpr int BM = 128, BN = 64, BK = 32, LDS_ = BK + 8;  // 40

__global__ __launch_bounds__(256) void gemm_bf16(
    const __nv_bfloat16* __restrict__ Ahg,
    const __nv_bfloat16* __restrict__ Alg,
    const __nv_bfloat16* __restrict__ Whg,
    const __nv_bfloat16* __restrict__ Wlg,
    const float* __restrict__ bias,
    float* __restrict__ C)
{
    __shared__ __nv_bfloat16 Ah[BM][LDS_], Al[BM][LDS_];
    __shared__ __nv_bfloat16 Bh[BN][LDS_], Bl[BN][LDS_];

    const int tid  = threadIdx.x;
    const int lane = tid & 31;
    const int wid  = tid >> 5;
    const int wm   = wid & 3;
    const int wn   = wid >> 2;
    const int grp  = lane >> 2;
    const int tig  = lane & 3;
    const int m0   = blockIdx.y * BM;
    const int n0   = blockIdx.x * BN;

    float acc[2][4][4];
#pragma unroll
    for (int mt = 0; mt < 2; mt++)
#pragma unroll
        for (int nt = 0; nt < 4; nt++)
#pragma unroll
            for (int i = 0; i < 4; i++) acc[mt][nt][i] = 0.0f;

    const int a_row_l = lane & 15;
    const int a_col_l = (lane >> 4) * 8;
    const int b_row_l = (lane & 7) + ((lane >> 4) << 3);
    const int b_col_l = ((lane >> 3) & 1) * 8;

    const uint32_t sAh = smem_u32(&Ah[0][0]);
    const uint32_t sAl = smem_u32(&Al[0][0]);
    const uint32_t sBh = smem_u32(&Bh[0][0]);
    const uint32_t sBl = smem_u32(&Bl[0][0]);

    for (int k0 = 0; k0 < EE; k0 += BK) {
        // A tiles (128 x 32), uint4 = 8 bf16: 2 per thread per plane
#pragma unroll
        for (int p = 0; p < 2; p++) {
            const int f   = tid + p * 256;
            const int row = f >> 2;
            const int kc  = (f & 3) * 8;
            const size_t g = (size_t)(m0 + row) * EE + k0 + kc;
            *reinterpret_cast<uint4*>(&Ah[row][kc]) =
                *reinterpret_cast<const uint4*>(&Ahg[g]);
            *reinterpret_cast<uint4*>(&Al[row][kc]) =
                *reinterpret_cast<const uint4*>(&Alg[g]);
        }
        // W tiles (64 x 32): 1 per thread per plane
        {
            const int row = tid >> 2;
            const int kc  = (tid & 3) * 8;
            const size_t g = (size_t)(n0 + row) * EE + k0 + kc;
            *reinterpret_cast<uint4*>(&Bh[row][kc]) =
                *reinterpret_cast<const uint4*>(&Whg[g]);
            *reinterpret_cast<uint4*>(&Bl[row][kc]) =
                *reinterpret_cast<const uint4*>(&Wlg[g]);
        }
        __syncthreads();

#pragma unroll
        for (int ks = 0; ks < 2; ks++) {
            const int kb = ks * 16;
            uint32_t ah[2][4], al[2][4];
#pragma unroll
            for (int mt = 0; mt < 2; mt++) {
                const uint32_t aoff =
                    ((wm * 32 + mt * 16 + a_row_l) * LDS_ + kb + a_col_l) * 2;
                ldmx4(ah[mt], sAh + aoff);
                ldmx4(al[mt], sAl + aoff);
            }
#pragma unroll
            for (int ntp = 0; ntp < 2; ntp++) {
                const uint32_t boff =
                    ((wn * 32 + ntp * 16 + b_row_l) * LDS_ + kb + b_col_l) * 2;
                uint32_t bh[4], bl[4];
                ldmx4(bh, sBh + boff);
                ldmx4(bl, sBl + boff);
#pragma unroll
                for (int j = 0; j < 2; j++) {
                    const int nt = ntp * 2 + j;
                    const uint32_t b0h = bh[2 * j], b1h = bh[2 * j + 1];
                    const uint32_t b0l = bl[2 * j], b1l = bl[2 * j + 1];
#pragma unroll
                    for (int mt = 0; mt < 2; mt++) {
                        mma_bf16(acc[mt][nt], ah[mt][0], ah[mt][1], ah[mt][2], ah[mt][3], b0h, b1h);
                        mma_bf16(acc[mt][nt], ah[mt][0], ah[mt][1], ah[mt][2], ah[mt][3], b0l, b1l);
                        mma_bf16(acc[mt][nt], al[mt][0], al[mt][1], al[mt][2], al[mt][3], b0h, b1h);
                    }
                }
            }
        }
        __syncthreads();
    }

#pragma unroll
    for (int mt = 0; mt < 2; mt++) {
        const int r0 = m0 + wm * 32 + mt * 16 + grp;
#pragma unroll
        for (int nt = 0; nt < 4; nt++) {
            const int c = n0 + wn * 32 + nt * 8 + 2 * tig;
            const float b0v = bias[c], b1v = bias[c + 1];
            float2 o0 = make_float2(acc[mt][nt][0] + b0v, acc[mt][nt][1] + b1v);
            float2 o1 = make_float2(acc[mt][nt][2] + b0v, acc[mt][nt][3] + b1v);
            *reinterpret_cast<float2*>(&C[(size_t)r0 * EE + c]) = o0;
            *reinterpret_cast<float2*>(&C[(size_t)(r0 + 8) * EE + c]) = o1;
        }
    }
}

// ---------------------------------------------------------------------------
// Sliding-window attention, 2 queries interleaved per warp step for ILP.
// Output written directly as bf16 hi/lo planes (feeds final GEMM).
// ---------------------------------------------------------------------------
constexpr int TL = 64;
constexpr int KROWS = TL + 32;   // 96

__global__ __launch_bounds__(256) void attn_window(
    const float* __restrict__ q,
    const float* __restrict__ k,
    const float* __restrict__ v,
    __nv_bfloat16* __restrict__ oh,
    __nv_bfloat16* __restrict__ ol)
{
    __shared__ float ks[KROWS][HD + 1];
    __shared__ float vs[KROWS][HD + 1];
    __shared__ float qs[TL][HD + 1];

    const int nh   = blockIdx.y;
    const int n    = nh / HH;
    const int h    = nh % HH;
    const int l0   = blockIdx.x * TL;
    const int tid  = threadIdx.x;
    const int lane = tid & 31;
    const int wid  = tid >> 5;

    const float scale = 0.17677669529663687f;  // 1/sqrt(32)

#pragma unroll
    for (int i = 0; i < KROWS / 8; i++) {
        const int r  = wid + i * 8;
        const int gl = l0 - 32 + r;
        float kv = 0.0f, vv = 0.0f;
        if (gl >= 0) {
            const size_t base = ((size_t)gl * NB + n) * EE + h * HD + lane;
            kv = k[base];
            vv = v[base];
        }
        ks[r][lane] = kv;
        vs[r][lane] = vv;
    }
#pragma unroll
    for (int i = 0; i < TL / 8; i++) {
        const int r = wid + i * 8;
        qs[r][lane] = q[((size_t)(l0 + r) * NB + n) * EE + h * HD + lane] * scale;
    }
    __syncthreads();

#pragma unroll 1
    for (int ii = 0; ii < 8; ii += 2) {
        const int qr0 = wid * 8 + ii;
        const int qr1 = qr0 + 1;
        const int l_0 = l0 + qr0, l_1 = l_0 + 1;
        const int li0 = qr0 + 32, li1 = qr1 + 32;

        // scores: lane t = tap t, two queries interleaved
        float s0 = 0.0f, s1 = 0.0f;
        const int kr0 = li0 - lane;
        const int kr1 = li1 - lane;
#pragma unroll
        for (int d = 0; d < HD; d++) {
            const float kv0 = ks[kr0][d];
            const float kv1 = ks[kr1][d];
            s0 += qs[qr0][d] * kv0;
            s1 += qs[qr1][d] * kv1;
        }
        if (lane > l_0) s0 = NEG;
        if (lane > l_1) s1 = NEG;

        // tap 32 pair via interleaved warp reductions
        float p0 = qs[qr0][lane] * ks[li0 - 32][lane];
        float p1 = qs[qr1][lane] * ks[li1 - 32][lane];
#pragma unroll
        for (int off = 16; off > 0; off >>= 1) {
            p0 += __shfl_xor_sync(0xFFFFFFFFu, p0, off);
            p1 += __shfl_xor_sync(0xFFFFFFFFu, p1, off);
        }
        const float s32_0 = (l_0 >= 32) ? p0 : NEG;
        const float s32_1 = (l_1 >= 32) ? p1 : NEG;

        // softmax pair
        float m0v = s0, m1v = s1;
#pragma unroll
        for (int off = 16; off > 0; off >>= 1) {
            m0v = fmaxf(m0v, __shfl_xor_sync(0xFFFFFFFFu, m0v, off));
            m1v = fmaxf(m1v, __shfl_xor_sync(0xFFFFFFFFu, m1v, off));
        }
        m0v = fmaxf(m0v, s32_0);
        m1v = fmaxf(m1v, s32_1);

        const float e0  = __expf(s0 - m0v);
        const float e1  = __expf(s1 - m1v);
        const float e32_0 = __expf(s32_0 - m0v);
        const float e32_1 = __expf(s32_1 - m1v);

        float d0 = e0, d1 = e1;
#pragma unroll
        for (int off = 16; off > 0; off >>= 1) {
            d0 += __shfl_xor_sync(0xFFFFFFFFu, d0, off);
            d1 += __shfl_xor_sync(0xFFFFFFFFu, d1, off);
        }
        const float inv0 = 1.0f / (d0 + e32_0);
        const float inv1 = 1.0f / (d1 + e32_1);

        // output pair: lane = dim
        float a0 = e32_0 * vs[li0 - 32][lane];
        float a1 = e32_1 * vs[li1 - 32][lane];
#pragma unroll
        for (int w = 0; w < 32; w++) {
            const float ew0 = __shfl_sync(0xFFFFFFFFu, e0, w);
            const float ew1 = __shfl_sync(0xFFFFFFFFu, e1, w);
            a0 += ew0 * vs[li0 - w][lane];
            a1 += ew1 * vs[li1 - w][lane];
        }

        const float r0 = a0 * inv0;
        const float r1 = a1 * inv1;
        const size_t ob0 = ((size_t)l_0 * NB + n) * EE + h * HD + lane;
        const size_t ob1 = ((size_t)l_1 * NB + n) * EE + h * HD + lane;
        __nv_bfloat16 h0, lo0, h1, lo1;
        cvt_hilo(r0, h0, lo0);
        cvt_hilo(r1, h1, lo1);
        oh[ob0] = h0; ol[ob0] = lo0;
        oh[ob1] = h1; ol[ob1] = lo1;
    }
}

// ---------------------------------------------------------------------------
extern "C" void kernel_launch(void* const* d_in, const int* in_sizes, int n_in,
                              void* d_out, int out_size)
{
    const float* query = (const float*)d_in[0];
    const float* key   = (const float*)d_in[1];
    const float* value = (const float*)d_in[2];
    const float* w_in  = (const float*)d_in[3];
    const float* b_in  = (const float*)d_in[4];
    const float* w_out = (const float*)d_in[5];
    const float* b_out = (const float*)d_in[6];
    float* out = (float*)d_out;

    float* f32 = nullptr;
    __nv_bfloat16 *hi = nullptr, *lo = nullptr, *wh = nullptr, *wl = nullptr;
    cudaGetSymbolAddress((void**)&f32, g_f32);
    cudaGetSymbolAddress((void**)&hi,  g_hi);
    cudaGetSymbolAddress((void**)&lo,  g_lo);
    cudaGetSymbolAddress((void**)&wh,  g_wh);
    cudaGetSymbolAddress((void**)&wl,  g_wl);

    float* gq = f32 + 0 * LNE;
    float* gk = f32 + 1 * LNE;
    float* gv = f32 + 2 * LNE;
    __nv_bfloat16 *qh = hi + 0 * LNE, *ql = lo + 0 * LNE;
    __nv_bfloat16 *kh = hi + 1 * LNE, *kl = lo + 1 * LNE;
    __nv_bfloat16 *vh = hi + 2 * LNE, *vl = lo + 2 * LNE;
    __nv_bfloat16 *ohp = hi + 3 * LNE, *olp = lo + 3 * LNE;
    __nv_bfloat16 *wih = wh, *wil = wl;                       // 768*256
    __nv_bfloat16 *woh = wh + 768 * 256, *wol = wl + 768 * 256;

    // Pre-convert GEMM inputs to bf16 hi/lo planes
    const int n4  = LNE / 4;
    cvt_planes<<<(n4 + 255) / 256, 256>>>(query, qh, ql, n4);
    cvt_planes<<<(n4 + 255) / 256, 256>>>(key,   kh, kl, n4);
    cvt_planes<<<(n4 + 255) / 256, 256>>>(value, vh, vl, n4);
    const int w4a = 768 * 256 / 4, w4b = 256 * 256 / 4;
    cvt_planes<<<(w4a + 255) / 256, 256>>>(w_in,  wih, wil, w4a);
    cvt_planes<<<(w4b + 255) / 256, 256>>>(w_out, woh, wol, w4b);

    dim3 ggrid(EE / BN, M / BM);   // (4, 128)

    gemm_bf16<<<ggrid, 256>>>(qh, ql, wih,               wil,               b_in,          gq);
    gemm_bf16<<<ggrid, 256>>>(kh, kl, wih + EE * EE,     wil + EE * EE,     b_in + EE,     gk);
    gemm_bf16<<<ggrid, 256>>>(vh, vl, wih + 2 * EE * EE, wil + 2 * EE * EE, b_in + 2 * EE, gv);

    attn_window<<<dim3(LL / TL, NB * HH), 256>>>(gq, gk, gv, ohp, olp);

    gemm_bf16<<<ggrid, 256>>>(ohp, olp, woh, wol, b_out, out);
}

// round 9
// speedup vs baseline: 2.2612x; 1.2152x over previous
#include <cuda_runtime.h>
#include <cuda_bf16.h>
#include <math.h>
#include <stdint.h>

// Problem constants
constexpr int LL   = 8192;
constexpr int NB   = 2;
constexpr int EE   = 256;
constexpr int HH   = 8;
constexpr int HD   = 32;
constexpr int M    = LL * NB;     // 16384
constexpr int LNE  = M * EE;
constexpr int WELEMS = 768 * 256 + 256 * 256;
constexpr float NEG = -1000000000.0f;

// Scratch
__device__ float                        g_f32[3 * LNE];   // gq, gk, gv fp32
__device__ __align__(16) __nv_bfloat16  g_hi[4 * LNE];    // q,k,v,attn-out hi
__device__ __align__(16) __nv_bfloat16  g_lo[4 * LNE];    // lo planes
__device__ __align__(16) __nv_bfloat16  g_wh[WELEMS];     // w_in | w_out hi
__device__ __align__(16) __nv_bfloat16  g_wl[WELEMS];     // lo

// ---------------------------------------------------------------------------
__device__ __forceinline__ void mma_bf16(float* c,
    uint32_t a0, uint32_t a1, uint32_t a2, uint32_t a3,
    uint32_t b0, uint32_t b1)
{
    asm volatile(
        "mma.sync.aligned.m16n8k16.row.col.f32.bf16.bf16.f32 "
        "{%0,%1,%2,%3}, {%4,%5,%6,%7}, {%8,%9}, {%0,%1,%2,%3};"
        : "+f"(c[0]), "+f"(c[1]), "+f"(c[2]), "+f"(c[3])
        : "r"(a0), "r"(a1), "r"(a2), "r"(a3), "r"(b0), "r"(b1));
}

__device__ __forceinline__ void ldmx4(uint32_t* r, uint32_t addr) {
    asm volatile("ldmatrix.sync.aligned.m8n8.x4.shared.b16 {%0,%1,%2,%3}, [%4];"
        : "=r"(r[0]), "=r"(r[1]), "=r"(r[2]), "=r"(r[3]) : "r"(addr));
}

__device__ __forceinline__ uint32_t smem_u32(const void* p) {
    uint32_t a;
    asm("{ .reg .u64 t; cvta.to.shared.u64 t, %1; cvt.u32.u64 %0, t; }"
        : "=r"(a) : "l"(p));
    return a;
}

__device__ __forceinline__ void cpasync16(uint32_t s, const void* g) {
    asm volatile("cp.async.cg.shared.global [%0], [%1], 16;" :: "r"(s), "l"(g));
}

__device__ __forceinline__ void cvt_hilo(float x, __nv_bfloat16& h, __nv_bfloat16& l) {
    h = __float2bfloat16_rn(x);
    l = __float2bfloat16_rn(x - __bfloat162float(h));
}

// ---------------------------------------------------------------------------
// Batched fp32 -> bf16 hi/lo for q,k,v (grid.z selects input)
// ---------------------------------------------------------------------------
__global__ __launch_bounds__(256) void cvt_qkv(
    const float* __restrict__ q, const float* __restrict__ k,
    const float* __restrict__ v,
    __nv_bfloat16* __restrict__ hp, __nv_bfloat16* __restrict__ lp)
{
    const int z = blockIdx.z;
    const float* x = (z == 0) ? q : (z == 1) ? k : v;
    const int i = blockIdx.x * 256 + threadIdx.x;  // exact: LNE/4 / 256 blocks
    float4 val = reinterpret_cast<const float4*>(x)[i];
    __nv_bfloat16 h[4], l[4];
    cvt_hilo(val.x, h[0], l[0]);
    cvt_hilo(val.y, h[1], l[1]);
    cvt_hilo(val.z, h[2], l[2]);
    cvt_hilo(val.w, h[3], l[3]);
    reinterpret_cast<uint2*>(hp + (size_t)z * LNE)[i] = *reinterpret_cast<uint2*>(h);
    reinterpret_cast<uint2*>(lp + (size_t)z * LNE)[i] = *reinterpret_cast<uint2*>(l);
}

__global__ __launch_bounds__(256) void cvt_planes(
    const float* __restrict__ x,
    __nv_bfloat16* __restrict__ hp, __nv_bfloat16* __restrict__ lp, int n4)
{
    const int i = blockIdx.x * 256 + threadIdx.x;
    if (i >= n4) return;
    float4 v = reinterpret_cast<const float4*>(x)[i];
    __nv_bfloat16 h[4], l[4];
    cvt_hilo(v.x, h[0], l[0]);
    cvt_hilo(v.y, h[1], l[1]);
    cvt_hilo(v.z, h[2], l[2]);
    cvt_hilo(v.w, h[3], l[3]);
    reinterpret_cast<uint2*>(hp)[i] = *reinterpret_cast<uint2*>(h);
    reinterpret_cast<uint2*>(lp)[i] = *reinterpret_cast<uint2*>(l);
}

// ---------------------------------------------------------------------------
// GEMM: C[m,n] = sum_k A[m,k]*W[n,k] + bias[n], bf16 hi/lo 3-term, cp.async
// double-buffered. grid.z batches independent (A, W, bias, C) problem slices:
//   A = Ab + z*LNE, W = Wb + z*EE*EE, bias = bb + z*EE, C = Cb + z*LNE.
// BM=128, BN=64, BK=32; 8 warps (4m x 2n), warp tile 32x32; LDS_=40 stride.
// ---------------------------------------------------------------------------
constexpr int BM = 128, BN = 64, BK = 32, LDS_ = BK + 8;  // 40
// dynamic smem byte layout (double-buffered)
constexpr int ABUF = BM * LDS_ * 2;            // 10240 per A plane buffer
constexpr int BBUF = BN * LDS_ * 2;            // 5120 per B plane buffer
constexpr int OFF_AH = 0;                      // [2][BM][LDS_]
constexpr int OFF_AL = 2 * ABUF;               // 20480
constexpr int OFF_BH = 4 * ABUF;               // 40960
constexpr int OFF_BL = OFF_BH + 2 * BBUF;      // 51200
constexpr int SMEM_GEMM = OFF_BL + 2 * BBUF;   // 61440

__global__ __launch_bounds__(256) void gemm_bf16(
    const __nv_bfloat16* __restrict__ Ab,
    const __nv_bfloat16* __restrict__ Alb,
    const __nv_bfloat16* __restrict__ Wb,
    const __nv_bfloat16* __restrict__ Wlb,
    const float* __restrict__ bb,
    float* __restrict__ Cb)
{
    extern __shared__ char dsm[];
    const uint32_t sbase = smem_u32(dsm);

    const int z = blockIdx.z;
    const __nv_bfloat16* Ahg = Ab  + (size_t)z * LNE;
    const __nv_bfloat16* Alg = Alb + (size_t)z * LNE;
    const __nv_bfloat16* Whg = Wb  + (size_t)z * EE * EE;
    const __nv_bfloat16* Wlg = Wlb + (size_t)z * EE * EE;
    const float* bias = bb + z * EE;
    float* C = Cb + (size_t)z * LNE;

    const int tid  = threadIdx.x;
    const int lane = tid & 31;
    const int wid  = tid >> 5;
    const int wm   = wid & 3;
    const int wn   = wid >> 2;
    const int grp  = lane >> 2;
    const int tig  = lane & 3;
    const int m0   = blockIdx.y * BM;
    const int n0   = blockIdx.x * BN;

    float acc[2][4][4];
#pragma unroll
    for (int mt = 0; mt < 2; mt++)
#pragma unroll
        for (int nt = 0; nt < 4; nt++)
#pragma unroll
            for (int i = 0; i < 4; i++) acc[mt][nt][i] = 0.0f;

    const int a_row_l = lane & 15;
    const int a_col_l = (lane >> 4) * 8;
    const int b_row_l = (lane & 7) + ((lane >> 4) << 3);
    const int b_col_l = ((lane >> 3) & 1) * 8;

    // staging indices
    const int sa_row = tid >> 2;            // with +64: two rows per thread
    const int sa_kc  = (tid & 3) * 8;
    const int sb_row = tid >> 2;
    const int sb_kc  = (tid & 3) * 8;

    auto stage = [&](int buf, int k0) {
#pragma unroll
        for (int p = 0; p < 2; p++) {
            const int row = sa_row + p * 64;
            const size_t g = (size_t)(m0 + row) * EE + k0 + sa_kc;
            const uint32_t s = sbase + OFF_AH + buf * ABUF + row * (LDS_ * 2) + sa_kc * 2;
            cpasync16(s, Ahg + g);
            cpasync16(s + (OFF_AL - OFF_AH), Alg + g);
        }
        {
            const size_t g = (size_t)(n0 + sb_row) * EE + k0 + sb_kc;
            const uint32_t s = sbase + OFF_BH + buf * BBUF + sb_row * (LDS_ * 2) + sb_kc * 2;
            cpasync16(s, Whg + g);
            cpasync16(s + (OFF_BL - OFF_BH), Wlg + g);
        }
        asm volatile("cp.async.commit_group;");
    };

    stage(0, 0);

    constexpr int NCH = EE / BK;  // 8
#pragma unroll 1
    for (int ch = 0; ch < NCH; ch++) {
        if (ch < NCH - 1) {
            stage((ch + 1) & 1, (ch + 1) * BK);
            asm volatile("cp.async.wait_group 1;");
        } else {
            asm volatile("cp.async.wait_group 0;");
        }
        __syncthreads();

        const int buf = ch & 1;
        const uint32_t sAh = sbase + OFF_AH + buf * ABUF;
        const uint32_t sAl = sbase + OFF_AL + buf * ABUF;
        const uint32_t sBh = sbase + OFF_BH + buf * BBUF;
        const uint32_t sBl = sbase + OFF_BL + buf * BBUF;

#pragma unroll
        for (int ks = 0; ks < 2; ks++) {
            const int kb = ks * 16;
            uint32_t ah[2][4], al[2][4];
#pragma unroll
            for (int mt = 0; mt < 2; mt++) {
                const uint32_t aoff =
                    ((wm * 32 + mt * 16 + a_row_l) * LDS_ + kb + a_col_l) * 2;
                ldmx4(ah[mt], sAh + aoff);
                ldmx4(al[mt], sAl + aoff);
            }
#pragma unroll
            for (int ntp = 0; ntp < 2; ntp++) {
                const uint32_t boff =
                    ((wn * 32 + ntp * 16 + b_row_l) * LDS_ + kb + b_col_l) * 2;
                uint32_t bh[4], bl[4];
                ldmx4(bh, sBh + boff);
                ldmx4(bl, sBl + boff);
#pragma unroll
                for (int j = 0; j < 2; j++) {
                    const int nt = ntp * 2 + j;
                    const uint32_t b0h = bh[2 * j], b1h = bh[2 * j + 1];
                    const uint32_t b0l = bl[2 * j], b1l = bl[2 * j + 1];
#pragma unroll
                    for (int mt = 0; mt < 2; mt++) {
                        mma_bf16(acc[mt][nt], ah[mt][0], ah[mt][1], ah[mt][2], ah[mt][3], b0h, b1h);
                        mma_bf16(acc[mt][nt], ah[mt][0], ah[mt][1], ah[mt][2], ah[mt][3], b0l, b1l);
                        mma_bf16(acc[mt][nt], al[mt][0], al[mt][1], al[mt][2], al[mt][3], b0h, b1h);
                    }
                }
            }
        }
        __syncthreads();
    }

#pragma unroll
    for (int mt = 0; mt < 2; mt++) {
        const int r0 = m0 + wm * 32 + mt * 16 + grp;
#pragma unroll
        for (int nt = 0; nt < 4; nt++) {
            const int c = n0 + wn * 32 + nt * 8 + 2 * tig;
            const float b0v = bias[c], b1v = bias[c + 1];
            float2 o0 = make_float2(acc[mt][nt][0] + b0v, acc[mt][nt][1] + b1v);
            float2 o1 = make_float2(acc[mt][nt][2] + b0v, acc[mt][nt][3] + b1v);
            *reinterpret_cast<float2*>(&C[(size_t)r0 * EE + c]) = o0;
            *reinterpret_cast<float2*>(&C[(size_t)(r0 + 8) * EE + c]) = o1;
        }
    }
}

// ---------------------------------------------------------------------------
// Sliding-window attention, 2-query ILP, softmax WITHOUT max subtraction
// (scores are O(+-15); exp cannot overflow fp32; softmax is shift-invariant).
// Emits bf16 hi/lo planes for the out-projection GEMM.
// ---------------------------------------------------------------------------
constexpr int TL = 64;
constexpr int KROWS = TL + 32;   // 96

__global__ __launch_bounds__(256) void attn_window(
    const float* __restrict__ q,
    const float* __restrict__ k,
    const float* __restrict__ v,
    __nv_bfloat16* __restrict__ oh,
    __nv_bfloat16* __restrict__ ol)
{
    __shared__ float ks[KROWS][HD + 1];
    __shared__ float vs[KROWS][HD + 1];
    __shared__ float qs[TL][HD + 1];

    const int nh   = blockIdx.y;
    const int n    = nh / HH;
    const int h    = nh % HH;
    const int l0   = blockIdx.x * TL;
    const int tid  = threadIdx.x;
    const int lane = tid & 31;
    const int wid  = tid >> 5;

    const float scale = 0.17677669529663687f;  // 1/sqrt(32)

#pragma unroll
    for (int i = 0; i < KROWS / 8; i++) {
        const int r  = wid + i * 8;
        const int gl = l0 - 32 + r;
        float kv = 0.0f, vv = 0.0f;
        if (gl >= 0) {
            const size_t base = ((size_t)gl * NB + n) * EE + h * HD + lane;
            kv = k[base];
            vv = v[base];
        }
        ks[r][lane] = kv;
        vs[r][lane] = vv;
    }
#pragma unroll
    for (int i = 0; i < TL / 8; i++) {
        const int r = wid + i * 8;
        qs[r][lane] = q[((size_t)(l0 + r) * NB + n) * EE + h * HD + lane] * scale;
    }
    __syncthreads();

#pragma unroll 1
    for (int ii = 0; ii < 8; ii += 2) {
        const int qr0 = wid * 8 + ii;
        const int qr1 = qr0 + 1;
        const int l_0 = l0 + qr0, l_1 = l_0 + 1;
        const int li0 = qr0 + 32, li1 = qr1 + 32;

        float s0 = 0.0f, s1 = 0.0f;
        const int kr0 = li0 - lane;
        const int kr1 = li1 - lane;
#pragma unroll
        for (int d = 0; d < HD; d++) {
            s0 += qs[qr0][d] * ks[kr0][d];
            s1 += qs[qr1][d] * ks[kr1][d];
        }
        if (lane > l_0) s0 = NEG;
        if (lane > l_1) s1 = NEG;

        float p0 = qs[qr0][lane] * ks[li0 - 32][lane];
        float p1 = qs[qr1][lane] * ks[li1 - 32][lane];
#pragma unroll
        for (int off = 16; off > 0; off >>= 1) {
            p0 += __shfl_xor_sync(0xFFFFFFFFu, p0, off);
            p1 += __shfl_xor_sync(0xFFFFFFFFu, p1, off);
        }
        const float s32_0 = (l_0 >= 32) ? p0 : NEG;
        const float s32_1 = (l_1 >= 32) ? p1 : NEG;

        // exp directly (masked lanes: exp(-1e9) underflows to 0)
        const float e0  = __expf(s0);
        const float e1  = __expf(s1);
        const float e32_0 = __expf(s32_0);
        const float e32_1 = __expf(s32_1);

        float d0 = e0, d1 = e1;
#pragma unroll
        for (int off = 16; off > 0; off >>= 1) {
            d0 += __shfl_xor_sync(0xFFFFFFFFu, d0, off);
            d1 += __shfl_xor_sync(0xFFFFFFFFu, d1, off);
        }
        const float inv0 = 1.0f / (d0 + e32_0);
        const float inv1 = 1.0f / (d1 + e32_1);

        float a0 = e32_0 * vs[li0 - 32][lane];
        float a1 = e32_1 * vs[li1 - 32][lane];
#pragma unroll
        for (int w = 0; w < 32; w++) {
            const float ew0 = __shfl_sync(0xFFFFFFFFu, e0, w);
            const float ew1 = __shfl_sync(0xFFFFFFFFu, e1, w);
            a0 += ew0 * vs[li0 - w][lane];
            a1 += ew1 * vs[li1 - w][lane];
        }

        const float r0 = a0 * inv0;
        const float r1 = a1 * inv1;
        const size_t ob0 = ((size_t)l_0 * NB + n) * EE + h * HD + lane;
        const size_t ob1 = ((size_t)l_1 * NB + n) * EE + h * HD + lane;
        __nv_bfloat16 h0, lo0, h1, lo1;
        cvt_hilo(r0, h0, lo0);
        cvt_hilo(r1, h1, lo1);
        oh[ob0] = h0; ol[ob0] = lo0;
        oh[ob1] = h1; ol[ob1] = lo1;
    }
}

// ---------------------------------------------------------------------------
extern "C" void kernel_launch(void* const* d_in, const int* in_sizes, int n_in,
                              void* d_out, int out_size)
{
    const float* query = (const float*)d_in[0];
    const float* key   = (const float*)d_in[1];
    const float* value = (const float*)d_in[2];
    const float* w_in  = (const float*)d_in[3];
    const float* b_in  = (const float*)d_in[4];
    const float* w_out = (const float*)d_in[5];
    const float* b_out = (const float*)d_in[6];
    float* out = (float*)d_out;

    float* f32 = nullptr;
    __nv_bfloat16 *hi = nullptr, *lo = nullptr, *wh = nullptr, *wl = nullptr;
    cudaGetSymbolAddress((void**)&f32, g_f32);
    cudaGetSymbolAddress((void**)&hi,  g_hi);
    cudaGetSymbolAddress((void**)&lo,  g_lo);
    cudaGetSymbolAddress((void**)&wh,  g_wh);
    cudaGetSymbolAddress((void**)&wl,  g_wl);

    __nv_bfloat16 *ohp = hi + 3 * (size_t)LNE, *olp = lo + 3 * (size_t)LNE;
    __nv_bfloat16 *wih = wh, *wil = wl;
    __nv_bfloat16 *woh = wh + 768 * 256, *wol = wl + 768 * 256;

    cudaFuncSetAttribute(gemm_bf16,
                         cudaFuncAttributeMaxDynamicSharedMemorySize, SMEM_GEMM);

    // Convert inputs to bf16 hi/lo planes
    cvt_qkv<<<dim3(LNE / 4 / 256, 1, 3), 256>>>(query, key, value, hi, lo);
    const int w4a = 768 * 256 / 4, w4b = 256 * 256 / 4;
    cvt_planes<<<(w4a + 255) / 256, 256>>>(w_in,  wih, wil, w4a);
    cvt_planes<<<(w4b + 255) / 256, 256>>>(w_out, woh, wol, w4b);

    // Batched q/k/v projection GEMMs (z = 0,1,2)
    gemm_bf16<<<dim3(EE / BN, M / BM, 3), 256, SMEM_GEMM>>>(
        hi, lo, wih, wil, b_in, f32);

    attn_window<<<dim3(LL / TL, NB * HH), 256>>>(
        f32, f32 + LNE, f32 + 2 * (size_t)LNE, ohp, olp);

    // Out-projection GEMM (z = 0)
    gemm_bf16<<<dim3(EE / BN, M / BM, 1), 256, SMEM_GEMM>>>(
        ohp, olp, woh, wol, b_out, out);
}

// round 10
// speedup vs baseline: 2.5410x; 1.1237x over previous
#include <cuda_runtime.h>
#include <cuda_bf16.h>
#include <math.h>
#include <stdint.h>

// Problem constants
constexpr int LL   = 8192;
constexpr int NB   = 2;
constexpr int EE   = 256;
constexpr int HH   = 8;
constexpr int HD   = 32;
constexpr int M    = LL * NB;     // 16384
constexpr int LNE  = M * EE;
constexpr int WELEMS = 768 * 256 + 256 * 256;
constexpr float NEG = -1000000000.0f;
constexpr float QSCALE = 0.17677669529663687f;  // 1/sqrt(32)

// Scratch planes
__device__ __align__(16) __nv_bfloat16 g_inh[3 * LNE];  // raw q,k,v hi
__device__ __align__(16) __nv_bfloat16 g_inl[3 * LNE];  // raw q,k,v lo
__device__ __align__(16) __nv_bfloat16 g_hi[4 * LNE];   // proj q,k,v + attn-out hi
__device__ __align__(16) __nv_bfloat16 g_lo[4 * LNE];   // lo
__device__ __align__(16) __nv_bfloat16 g_wh[WELEMS];
__device__ __align__(16) __nv_bfloat16 g_wl[WELEMS];

// ---------------------------------------------------------------------------
__device__ __forceinline__ void mma_bf16(float* c,
    uint32_t a0, uint32_t a1, uint32_t a2, uint32_t a3,
    uint32_t b0, uint32_t b1)
{
    asm volatile(
        "mma.sync.aligned.m16n8k16.row.col.f32.bf16.bf16.f32 "
        "{%0,%1,%2,%3}, {%4,%5,%6,%7}, {%8,%9}, {%0,%1,%2,%3};"
        : "+f"(c[0]), "+f"(c[1]), "+f"(c[2]), "+f"(c[3])
        : "r"(a0), "r"(a1), "r"(a2), "r"(a3), "r"(b0), "r"(b1));
}
__device__ __forceinline__ void ldmx4(uint32_t* r, uint32_t addr) {
    asm volatile("ldmatrix.sync.aligned.m8n8.x4.shared.b16 {%0,%1,%2,%3}, [%4];"
        : "=r"(r[0]), "=r"(r[1]), "=r"(r[2]), "=r"(r[3]) : "r"(addr));
}
__device__ __forceinline__ void ldmx4t(uint32_t* r, uint32_t addr) {
    asm volatile("ldmatrix.sync.aligned.m8n8.x4.trans.shared.b16 {%0,%1,%2,%3}, [%4];"
        : "=r"(r[0]), "=r"(r[1]), "=r"(r[2]), "=r"(r[3]) : "r"(addr));
}
__device__ __forceinline__ uint32_t smem_u32(const void* p) {
    uint32_t a;
    asm("{ .reg .u64 t; cvta.to.shared.u64 t, %1; cvt.u32.u64 %0, t; }"
        : "=r"(a) : "l"(p));
    return a;
}
__device__ __forceinline__ void cpasync16(uint32_t s, const void* g) {
    asm volatile("cp.async.cg.shared.global [%0], [%1], 16;" :: "r"(s), "l"(g));
}
__device__ __forceinline__ void cvt_hilo(float x, __nv_bfloat16& h, __nv_bfloat16& l) {
    h = __float2bfloat16_rn(x);
    l = __float2bfloat16_rn(x - __bfloat162float(h));
}
// pack two floats into bf16 hi-pair and lo-pair words
__device__ __forceinline__ void pack2(float a, float b, uint32_t& hi, uint32_t& lo) {
    __nv_bfloat16 ha, la, hb, lb;
    cvt_hilo(a, ha, la);
    cvt_hilo(b, hb, lb);
    __nv_bfloat162 H; H.x = ha; H.y = hb;
    __nv_bfloat162 L; L.x = la; L.y = lb;
    hi = *reinterpret_cast<uint32_t*>(&H);
    lo = *reinterpret_cast<uint32_t*>(&L);
}

// ---------------------------------------------------------------------------
__global__ __launch_bounds__(256) void cvt_qkv(
    const float* __restrict__ q, const float* __restrict__ k,
    const float* __restrict__ v,
    __nv_bfloat16* __restrict__ hp, __nv_bfloat16* __restrict__ lp)
{
    const int z = blockIdx.z;
    const float* x = (z == 0) ? q : (z == 1) ? k : v;
    const int i = blockIdx.x * 256 + threadIdx.x;
    float4 val = reinterpret_cast<const float4*>(x)[i];
    __nv_bfloat16 h[4], l[4];
    cvt_hilo(val.x, h[0], l[0]);
    cvt_hilo(val.y, h[1], l[1]);
    cvt_hilo(val.z, h[2], l[2]);
    cvt_hilo(val.w, h[3], l[3]);
    reinterpret_cast<uint2*>(hp + (size_t)z * LNE)[i] = *reinterpret_cast<uint2*>(h);
    reinterpret_cast<uint2*>(lp + (size_t)z * LNE)[i] = *reinterpret_cast<uint2*>(l);
}

__global__ __launch_bounds__(256) void cvt_planes(
    const float* __restrict__ x,
    __nv_bfloat16* __restrict__ hp, __nv_bfloat16* __restrict__ lp, int n4)
{
    const int i = blockIdx.x * 256 + threadIdx.x;
    if (i >= n4) return;
    float4 v = reinterpret_cast<const float4*>(x)[i];
    __nv_bfloat16 h[4], l[4];
    cvt_hilo(v.x, h[0], l[0]);
    cvt_hilo(v.y, h[1], l[1]);
    cvt_hilo(v.z, h[2], l[2]);
    cvt_hilo(v.w, h[3], l[3]);
    reinterpret_cast<uint2*>(hp)[i] = *reinterpret_cast<uint2*>(h);
    reinterpret_cast<uint2*>(lp)[i] = *reinterpret_cast<uint2*>(l);
}

// ---------------------------------------------------------------------------
// GEMM (bf16 hi/lo 3-term, cp.async double-buffered, grid.z batched).
// mode 0: write fp32 C. mode 1: write bf16 hi/lo planes, q-scale on z==0.
// ---------------------------------------------------------------------------
constexpr int BM = 128, BN = 64, BK = 32, LDS_ = BK + 8;  // 40
constexpr int ABUF = BM * LDS_ * 2;
constexpr int BBUF = BN * LDS_ * 2;
constexpr int OFF_AH = 0;
constexpr int OFF_AL = 2 * ABUF;
constexpr int OFF_BH = 4 * ABUF;
constexpr int OFF_BL = OFF_BH + 2 * BBUF;
constexpr int SMEM_GEMM = OFF_BL + 2 * BBUF;   // 61440

__global__ __launch_bounds__(256) void gemm_bf16(
    const __nv_bfloat16* __restrict__ Ab,
    const __nv_bfloat16* __restrict__ Alb,
    const __nv_bfloat16* __restrict__ Wb,
    const __nv_bfloat16* __restrict__ Wlb,
    const float* __restrict__ bb,
    float* __restrict__ Cf,
    __nv_bfloat16* __restrict__ Chp,
    __nv_bfloat16* __restrict__ Clp,
    int mode)
{
    extern __shared__ char dsm[];
    const uint32_t sbase = smem_u32(dsm);

    const int z = blockIdx.z;
    const __nv_bfloat16* Ahg = Ab  + (size_t)z * LNE;
    const __nv_bfloat16* Alg = Alb + (size_t)z * LNE;
    const __nv_bfloat16* Whg = Wb  + (size_t)z * EE * EE;
    const __nv_bfloat16* Wlg = Wlb + (size_t)z * EE * EE;
    const float* bias = bb + z * EE;

    const int tid  = threadIdx.x;
    const int lane = tid & 31;
    const int wid  = tid >> 5;
    const int wm   = wid & 3;
    const int wn   = wid >> 2;
    const int grp  = lane >> 2;
    const int tig  = lane & 3;
    const int m0   = blockIdx.y * BM;
    const int n0   = blockIdx.x * BN;

    float acc[2][4][4];
#pragma unroll
    for (int mt = 0; mt < 2; mt++)
#pragma unroll
        for (int nt = 0; nt < 4; nt++)
#pragma unroll
            for (int i = 0; i < 4; i++) acc[mt][nt][i] = 0.0f;

    const int a_row_l = lane & 15;
    const int a_col_l = (lane >> 4) * 8;
    const int b_row_l = (lane & 7) + ((lane >> 4) << 3);
    const int b_col_l = ((lane >> 3) & 1) * 8;

    const int sa_row = tid >> 2;
    const int sa_kc  = (tid & 3) * 8;

    auto stage = [&](int buf, int k0) {
#pragma unroll
        for (int p = 0; p < 2; p++) {
            const int row = sa_row + p * 64;
            const size_t g = (size_t)(m0 + row) * EE + k0 + sa_kc;
            const uint32_t s = sbase + OFF_AH + buf * ABUF + row * (LDS_ * 2) + sa_kc * 2;
            cpasync16(s, Ahg + g);
            cpasync16(s + (OFF_AL - OFF_AH), Alg + g);
        }
        {
            const size_t g = (size_t)(n0 + sa_row) * EE + k0 + sa_kc;
            const uint32_t s = sbase + OFF_BH + buf * BBUF + sa_row * (LDS_ * 2) + sa_kc * 2;
            cpasync16(s, Whg + g);
            cpasync16(s + (OFF_BL - OFF_BH), Wlg + g);
        }
        asm volatile("cp.async.commit_group;");
    };

    stage(0, 0);
    constexpr int NCH = EE / BK;
#pragma unroll 1
    for (int ch = 0; ch < NCH; ch++) {
        if (ch < NCH - 1) {
            stage((ch + 1) & 1, (ch + 1) * BK);
            asm volatile("cp.async.wait_group 1;");
        } else {
            asm volatile("cp.async.wait_group 0;");
        }
        __syncthreads();

        const int buf = ch & 1;
        const uint32_t sAh = sbase + OFF_AH + buf * ABUF;
        const uint32_t sAl = sbase + OFF_AL + buf * ABUF;
        const uint32_t sBh = sbase + OFF_BH + buf * BBUF;
        const uint32_t sBl = sbase + OFF_BL + buf * BBUF;

#pragma unroll
        for (int ks = 0; ks < 2; ks++) {
            const int kb = ks * 16;
            uint32_t ah[2][4], al[2][4];
#pragma unroll
            for (int mt = 0; mt < 2; mt++) {
                const uint32_t aoff =
                    ((wm * 32 + mt * 16 + a_row_l) * LDS_ + kb + a_col_l) * 2;
                ldmx4(ah[mt], sAh + aoff);
                ldmx4(al[mt], sAl + aoff);
            }
#pragma unroll
            for (int ntp = 0; ntp < 2; ntp++) {
                const uint32_t boff =
                    ((wn * 32 + ntp * 16 + b_row_l) * LDS_ + kb + b_col_l) * 2;
                uint32_t bh[4], bl[4];
                ldmx4(bh, sBh + boff);
                ldmx4(bl, sBl + boff);
#pragma unroll
                for (int j = 0; j < 2; j++) {
                    const int nt = ntp * 2 + j;
                    const uint32_t b0h = bh[2 * j], b1h = bh[2 * j + 1];
                    const uint32_t b0l = bl[2 * j], b1l = bl[2 * j + 1];
#pragma unroll
                    for (int mt = 0; mt < 2; mt++) {
                        mma_bf16(acc[mt][nt], ah[mt][0], ah[mt][1], ah[mt][2], ah[mt][3], b0h, b1h);
                        mma_bf16(acc[mt][nt], ah[mt][0], ah[mt][1], ah[mt][2], ah[mt][3], b0l, b1l);
                        mma_bf16(acc[mt][nt], al[mt][0], al[mt][1], al[mt][2], al[mt][3], b0h, b1h);
                    }
                }
            }
        }
        __syncthreads();
    }

    if (mode == 0) {
        float* C = Cf;
#pragma unroll
        for (int mt = 0; mt < 2; mt++) {
            const int r0 = m0 + wm * 32 + mt * 16 + grp;
#pragma unroll
            for (int nt = 0; nt < 4; nt++) {
                const int c = n0 + wn * 32 + nt * 8 + 2 * tig;
                const float b0v = bias[c], b1v = bias[c + 1];
                float2 o0 = make_float2(acc[mt][nt][0] + b0v, acc[mt][nt][1] + b1v);
                float2 o1 = make_float2(acc[mt][nt][2] + b0v, acc[mt][nt][3] + b1v);
                *reinterpret_cast<float2*>(&C[(size_t)r0 * EE + c]) = o0;
                *reinterpret_cast<float2*>(&C[(size_t)(r0 + 8) * EE + c]) = o1;
            }
        }
    } else {
        const float sc = (z == 0) ? QSCALE : 1.0f;
        __nv_bfloat16* Ch = Chp + (size_t)z * LNE;
        __nv_bfloat16* Cl = Clp + (size_t)z * LNE;
#pragma unroll
        for (int mt = 0; mt < 2; mt++) {
            const int r0 = m0 + wm * 32 + mt * 16 + grp;
#pragma unroll
            for (int nt = 0; nt < 4; nt++) {
                const int c = n0 + wn * 32 + nt * 8 + 2 * tig;
                const float b0v = bias[c], b1v = bias[c + 1];
                uint32_t hi0, lo0, hi1, lo1;
                pack2((acc[mt][nt][0] + b0v) * sc, (acc[mt][nt][1] + b1v) * sc, hi0, lo0);
                pack2((acc[mt][nt][2] + b0v) * sc, (acc[mt][nt][3] + b1v) * sc, hi1, lo1);
                *reinterpret_cast<uint32_t*>(&Ch[(size_t)r0 * EE + c]) = hi0;
                *reinterpret_cast<uint32_t*>(&Cl[(size_t)r0 * EE + c]) = lo0;
                *reinterpret_cast<uint32_t*>(&Ch[(size_t)(r0 + 8) * EE + c]) = hi1;
                *reinterpret_cast<uint32_t*>(&Cl[(size_t)(r0 + 8) * EE + c]) = lo1;
            }
        }
    }
}

// ---------------------------------------------------------------------------
// MMA sliding-window attention.
// Block = 64 queries for one (n, h). S(64x96)=Q K^T, P=exp(masked S),
// O(64x32)=P V, denom = rowsum(P), all bf16 hi/lo 3-term on tensor cores.
// ---------------------------------------------------------------------------
constexpr int TLQ = 64, KR = 96;
constexpr int KSTR = 40;    // row stride (bf16) for Q/K/V tiles
constexpr int PSTR = 104;   // row stride for P (96 + 8)
constexpr int AOFF_QH = 0;
constexpr int AOFF_QL = AOFF_QH + TLQ * KSTR * 2;   // 5120
constexpr int AOFF_KH = AOFF_QL + TLQ * KSTR * 2;   // 10240
constexpr int AOFF_KL = AOFF_KH + KR * KSTR * 2;    // 17920
constexpr int AOFF_VH = AOFF_KL + KR * KSTR * 2;    // 25600
constexpr int AOFF_VL = AOFF_VH + KR * KSTR * 2;    // 33280
constexpr int AOFF_PH = AOFF_VL + KR * KSTR * 2;    // 40960
constexpr int AOFF_PL = AOFF_PH + TLQ * PSTR * 2;   // 54272
constexpr int AOFF_DEN = AOFF_PL + TLQ * PSTR * 2;  // 67584
constexpr int SMEM_ATTN = AOFF_DEN + TLQ * 2 * 4;   // 68096

__global__ __launch_bounds__(256) void attn_mma(
    const __nv_bfloat16* __restrict__ qh, const __nv_bfloat16* __restrict__ ql,
    const __nv_bfloat16* __restrict__ kh, const __nv_bfloat16* __restrict__ kl,
    const __nv_bfloat16* __restrict__ vh, const __nv_bfloat16* __restrict__ vl,
    __nv_bfloat16* __restrict__ oh, __nv_bfloat16* __restrict__ ol)
{
    extern __shared__ char dsm[];
    const uint32_t sb = smem_u32(dsm);

    const int nhid = blockIdx.y;
    const int n    = nhid / HH;
    const int h    = nhid % HH;
    const int l0   = blockIdx.x * TLQ;
    const int tid  = threadIdx.x;
    const int lane = tid & 31;
    const int wid  = tid >> 5;
    const int mt   = wid & 3;      // m-tile (16 queries)
    const int nhf  = wid >> 2;     // n-half
    const int grp  = lane >> 2;
    const int tig  = lane & 3;

    // --- stage Q (64 rows x 32 bf16, 4 chunks/row/plane)
    {
        const int row = tid >> 2, ch = tid & 3;
        const size_t src = ((size_t)(l0 + row) * NB + n) * EE + h * HD + ch * 8;
        const uint32_t dst = sb + AOFF_QH + row * (KSTR * 2) + ch * 16;
        cpasync16(dst, qh + src);
        cpasync16(dst + (AOFF_QL - AOFF_QH), ql + src);
    }
    // --- stage K, V (96 rows; gl<0 rows zero-filled)
#pragma unroll
    for (int i = 0; i < 2; i++) {
        const int idx = tid + i * 256;
        if (idx < KR * 4) {
            const int row = idx >> 2, ch = idx & 3;
            const int gl = l0 - 32 + row;
            const uint32_t dk = sb + AOFF_KH + row * (KSTR * 2) + ch * 16;
            const uint32_t dv = sb + AOFF_VH + row * (KSTR * 2) + ch * 16;
            if (gl >= 0) {
                const size_t src = ((size_t)gl * NB + n) * EE + h * HD + ch * 8;
                cpasync16(dk, kh + src);
                cpasync16(dk + (AOFF_KL - AOFF_KH), kl + src);
                cpasync16(dv, vh + src);
                cpasync16(dv + (AOFF_VL - AOFF_VH), vl + src);
            } else {
                const uint4 z4 = make_uint4(0, 0, 0, 0);
                const int bo = row * (KSTR * 2) + ch * 16;
                *reinterpret_cast<uint4*>(dsm + AOFF_KH + bo) = z4;
                *reinterpret_cast<uint4*>(dsm + AOFF_KL + bo) = z4;
                *reinterpret_cast<uint4*>(dsm + AOFF_VH + bo) = z4;
                *reinterpret_cast<uint4*>(dsm + AOFF_VL + bo) = z4;
            }
        }
    }
    asm volatile("cp.async.commit_group;");
    asm volatile("cp.async.wait_group 0;");
    __syncthreads();

    const int a_row_l = lane & 15;
    const int a_col_l = (lane >> 4) * 8;
    const int b_row_l = (lane & 7) + ((lane >> 4) << 3);
    const int b_col_l = ((lane >> 3) & 1) * 8;

    // --- score GEMM: warp (mt, nhf): rows mt*16..+16, cols nhf*48..+48
    float scacc[6][4];
#pragma unroll
    for (int t = 0; t < 6; t++)
#pragma unroll
        for (int i = 0; i < 4; i++) scacc[t][i] = 0.0f;

#pragma unroll
    for (int ks = 0; ks < 2; ks++) {
        const int kb = ks * 16;
        uint32_t qa[4], qb[4];
        const uint32_t aoff = (mt * 16 + a_row_l) * (KSTR * 2) + (kb + a_col_l) * 2;
        ldmx4(qa, sb + AOFF_QH + aoff);
        ldmx4(qb, sb + AOFF_QL + aoff);
#pragma unroll
        for (int p = 0; p < 3; p++) {
            const int nb = nhf * 48 + p * 16;
            const uint32_t boff = (nb + b_row_l) * (KSTR * 2) + (kb + b_col_l) * 2;
            uint32_t kbh[4], kbl[4];
            ldmx4(kbh, sb + AOFF_KH + boff);
            ldmx4(kbl, sb + AOFF_KL + boff);
#pragma unroll
            for (int j = 0; j < 2; j++) {
                const int t = p * 2 + j;
                mma_bf16(scacc[t], qa[0], qa[1], qa[2], qa[3], kbh[2 * j], kbh[2 * j + 1]);
                mma_bf16(scacc[t], qa[0], qa[1], qa[2], qa[3], kbl[2 * j], kbl[2 * j + 1]);
                mma_bf16(scacc[t], qb[0], qb[1], qb[2], qb[3], kbh[2 * j], kbh[2 * j + 1]);
            }
        }
    }

    // --- mask + exp + store P (bf16 hi/lo) + denominator partials
    const int r0 = mt * 16 + grp;
    const int r1 = r0 + 8;
    float sA = 0.0f, sB = 0.0f;
#pragma unroll
    for (int t = 0; t < 6; t++) {
        const int c0 = nhf * 48 + t * 8 + 2 * tig;
        const int c1 = c0 + 1;
        const float m00 = (c0 >= r0 && c0 <= r0 + 32 && l0 + c0 >= 32) ? 0.0f : NEG;
        const float m01 = (c1 >= r0 && c1 <= r0 + 32 && l0 + c1 >= 32) ? 0.0f : NEG;
        const float m10 = (c0 >= r1 && c0 <= r1 + 32 && l0 + c0 >= 32) ? 0.0f : NEG;
        const float m11 = (c1 >= r1 && c1 <= r1 + 32 && l0 + c1 >= 32) ? 0.0f : NEG;
        const float e00 = __expf(scacc[t][0] + m00);
        const float e01 = __expf(scacc[t][1] + m01);
        const float e10 = __expf(scacc[t][2] + m10);
        const float e11 = __expf(scacc[t][3] + m11);
        sA += e00 + e01;
        sB += e10 + e11;
        uint32_t hi0, lo0, hi1, lo1;
        pack2(e00, e01, hi0, lo0);
        pack2(e10, e11, hi1, lo1);
        const int bo0 = (r0 * PSTR + c0) * 2;
        const int bo1 = (r1 * PSTR + c0) * 2;
        *reinterpret_cast<uint32_t*>(dsm + AOFF_PH + bo0) = hi0;
        *reinterpret_cast<uint32_t*>(dsm + AOFF_PL + bo0) = lo0;
        *reinterpret_cast<uint32_t*>(dsm + AOFF_PH + bo1) = hi1;
        *reinterpret_cast<uint32_t*>(dsm + AOFF_PL + bo1) = lo1;
    }
    sA += __shfl_xor_sync(0xFFFFFFFFu, sA, 1);
    sA += __shfl_xor_sync(0xFFFFFFFFu, sA, 2);
    sB += __shfl_xor_sync(0xFFFFFFFFu, sB, 1);
    sB += __shfl_xor_sync(0xFFFFFFFFu, sB, 2);
    if (tig == 0) {
        *reinterpret_cast<float*>(dsm + AOFF_DEN + (r0 * 2 + nhf) * 4) = sA;
        *reinterpret_cast<float*>(dsm + AOFF_DEN + (r1 * 2 + nhf) * 4) = sB;
    }
    __syncthreads();

    // --- output GEMM: O(rows mt*16..+16, dims nhf*16..+16) = P * V
    float oacc[2][4];
#pragma unroll
    for (int j = 0; j < 2; j++)
#pragma unroll
        for (int i = 0; i < 4; i++) oacc[j][i] = 0.0f;

#pragma unroll
    for (int ks = 0; ks < 6; ks++) {
        const int kb = ks * 16;
        uint32_t pa[4], pb[4];
        const uint32_t aoff = (mt * 16 + a_row_l) * (PSTR * 2) + (kb + a_col_l) * 2;
        ldmx4(pa, sb + AOFF_PH + aoff);
        ldmx4(pb, sb + AOFF_PL + aoff);
        // V^T fragments via trans ldmatrix: rows = keys kb..kb+15, dims nhf*16..+16
        const uint32_t voff = (kb + a_row_l) * (KSTR * 2) + nhf * 32 + (lane >> 4) * 16;
        uint32_t vth[4], vtl[4];
        ldmx4t(vth, sb + AOFF_VH + voff);
        ldmx4t(vtl, sb + AOFF_VL + voff);
#pragma unroll
        for (int j = 0; j < 2; j++) {
            mma_bf16(oacc[j], pa[0], pa[1], pa[2], pa[3], vth[2 * j], vth[2 * j + 1]);
            mma_bf16(oacc[j], pa[0], pa[1], pa[2], pa[3], vtl[2 * j], vtl[2 * j + 1]);
            mma_bf16(oacc[j], pb[0], pb[1], pb[2], pb[3], vth[2 * j], vth[2 * j + 1]);
        }
    }

    // --- normalize + store bf16 hi/lo planes
    const float dA = *reinterpret_cast<float*>(dsm + AOFF_DEN + r0 * 8) +
                     *reinterpret_cast<float*>(dsm + AOFF_DEN + r0 * 8 + 4);
    const float dB = *reinterpret_cast<float*>(dsm + AOFF_DEN + r1 * 8) +
                     *reinterpret_cast<float*>(dsm + AOFF_DEN + r1 * 8 + 4);
    const float invA = 1.0f / dA;
    const float invB = 1.0f / dB;
    const size_t base0 = ((size_t)(l0 + r0) * NB + n) * EE + h * HD;
    const size_t base1 = ((size_t)(l0 + r1) * NB + n) * EE + h * HD;
#pragma unroll
    for (int j = 0; j < 2; j++) {
        const int d0 = nhf * 16 + j * 8 + 2 * tig;
        uint32_t hi0, lo0, hi1, lo1;
        pack2(oacc[j][0] * invA, oacc[j][1] * invA, hi0, lo0);
        pack2(oacc[j][2] * invB, oacc[j][3] * invB, hi1, lo1);
        *reinterpret_cast<uint32_t*>(oh + base0 + d0) = hi0;
        *reinterpret_cast<uint32_t*>(ol + base0 + d0) = lo0;
        *reinterpret_cast<uint32_t*>(oh + base1 + d0) = hi1;
        *reinterpret_cast<uint32_t*>(ol + base1 + d0) = lo1;
    }
}

// ---------------------------------------------------------------------------
extern "C" void kernel_launch(void* const* d_in, const int* in_sizes, int n_in,
                              void* d_out, int out_size)
{
    const float* query = (const float*)d_in[0];
    const float* key   = (const float*)d_in[1];
    const float* value = (const float*)d_in[2];
    const float* w_in  = (const float*)d_in[3];
    const float* b_in  = (const float*)d_in[4];
    const float* w_out = (const float*)d_in[5];
    const float* b_out = (const float*)d_in[6];
    float* out = (float*)d_out;

    __nv_bfloat16 *inh = nullptr, *inl = nullptr, *hi = nullptr, *lo = nullptr;
    __nv_bfloat16 *wh = nullptr, *wl = nullptr;
    cudaGetSymbolAddress((void**)&inh, g_inh);
    cudaGetSymbolAddress((void**)&inl, g_inl);
    cudaGetSymbolAddress((void**)&hi,  g_hi);
    cudaGetSymbolAddress((void**)&lo,  g_lo);
    cudaGetSymbolAddress((void**)&wh,  g_wh);
    cudaGetSymbolAddress((void**)&wl,  g_wl);

    __nv_bfloat16 *wih = wh, *wil = wl;
    __nv_bfloat16 *woh = wh + 768 * 256, *wol = wl + 768 * 256;
    __nv_bfloat16 *ohp = hi + 3 * (size_t)LNE, *olp = lo + 3 * (size_t)LNE;

    cudaFuncSetAttribute(gemm_bf16,
        cudaFuncAttributeMaxDynamicSharedMemorySize, SMEM_GEMM);
    cudaFuncSetAttribute(attn_mma,
        cudaFuncAttributeMaxDynamicSharedMemorySize, SMEM_ATTN);

    // raw inputs -> bf16 hi/lo planes
    cvt_qkv<<<dim3(LNE / 4 / 256, 1, 3), 256>>>(query, key, value, inh, inl);
    const int w4a = 768 * 256 / 4, w4b = 256 * 256 / 4;
    cvt_planes<<<(w4a + 255) / 256, 256>>>(w_in,  wih, wil, w4a);
    cvt_planes<<<(w4b + 255) / 256, 256>>>(w_out, woh, wol, w4b);

    // batched q/k/v projections -> hi/lo planes (q scaled)
    gemm_bf16<<<dim3(EE / BN, M / BM, 3), 256, SMEM_GEMM>>>(
        inh, inl, wih, wil, b_in, nullptr, hi, lo, 1);

    // MMA attention: planes 0,1,2 -> plane 3
    attn_mma<<<dim3(LL / TLQ, NB * HH), 256, SMEM_ATTN>>>(
        hi, lo, hi + LNE, lo + LNE, hi + 2 * (size_t)LNE, lo + 2 * (size_t)LNE,
        ohp, olp);

    // out projection -> fp32 out
    gemm_bf16<<<dim3(EE / BN, M / BM, 1), 256, SMEM_GEMM>>>(
        ohp, olp, woh, wol, b_out, out, nullptr, nullptr, 0);
}

// round 11
// speedup vs baseline: 2.6412x; 1.0395x over previous
#include <cuda_runtime.h>
#include <cuda_bf16.h>
#include <math.h>
#include <stdint.h>

// Problem constants
constexpr int LL   = 8192;
constexpr int NB   = 2;
constexpr int EE   = 256;
constexpr int HH   = 8;
constexpr int HD   = 32;
constexpr int M    = LL * NB;     // 16384
constexpr int LNE  = M * EE;
constexpr int WELEMS = 768 * 256 + 256 * 256;
constexpr float NEG = -1000000000.0f;
constexpr float QSCALE = 0.17677669529663687f;  // 1/sqrt(32)

// Scratch planes
__device__ __align__(16) __nv_bfloat16 g_inh[3 * LNE];  // raw q,k,v hi
__device__ __align__(16) __nv_bfloat16 g_inl[3 * LNE];  // raw q,k,v lo
__device__ __align__(16) __nv_bfloat16 g_hi[4 * LNE];   // proj q,k,v + attn-out hi
__device__ __align__(16) __nv_bfloat16 g_lo[4 * LNE];   // lo
__device__ __align__(16) __nv_bfloat16 g_wh[WELEMS];
__device__ __align__(16) __nv_bfloat16 g_wl[WELEMS];

// ---------------------------------------------------------------------------
__device__ __forceinline__ void mma_bf16(float* c,
    uint32_t a0, uint32_t a1, uint32_t a2, uint32_t a3,
    uint32_t b0, uint32_t b1)
{
    asm volatile(
        "mma.sync.aligned.m16n8k16.row.col.f32.bf16.bf16.f32 "
        "{%0,%1,%2,%3}, {%4,%5,%6,%7}, {%8,%9}, {%0,%1,%2,%3};"
        : "+f"(c[0]), "+f"(c[1]), "+f"(c[2]), "+f"(c[3])
        : "r"(a0), "r"(a1), "r"(a2), "r"(a3), "r"(b0), "r"(b1));
}
__device__ __forceinline__ void ldmx4(uint32_t* r, uint32_t addr) {
    asm volatile("ldmatrix.sync.aligned.m8n8.x4.shared.b16 {%0,%1,%2,%3}, [%4];"
        : "=r"(r[0]), "=r"(r[1]), "=r"(r[2]), "=r"(r[3]) : "r"(addr));
}
__device__ __forceinline__ void ldmx4t(uint32_t* r, uint32_t addr) {
    asm volatile("ldmatrix.sync.aligned.m8n8.x4.trans.shared.b16 {%0,%1,%2,%3}, [%4];"
        : "=r"(r[0]), "=r"(r[1]), "=r"(r[2]), "=r"(r[3]) : "r"(addr));
}
__device__ __forceinline__ uint32_t smem_u32(const void* p) {
    uint32_t a;
    asm("{ .reg .u64 t; cvta.to.shared.u64 t, %1; cvt.u32.u64 %0, t; }"
        : "=r"(a) : "l"(p));
    return a;
}
__device__ __forceinline__ void cpasync16(uint32_t s, const void* g) {
    asm volatile("cp.async.cg.shared.global [%0], [%1], 16;" :: "r"(s), "l"(g));
}
__device__ __forceinline__ void cvt_hilo(float x, __nv_bfloat16& h, __nv_bfloat16& l) {
    h = __float2bfloat16_rn(x);
    l = __float2bfloat16_rn(x - __bfloat162float(h));
}
__device__ __forceinline__ void pack2(float a, float b, uint32_t& hi, uint32_t& lo) {
    __nv_bfloat16 ha, la, hb, lb;
    cvt_hilo(a, ha, la);
    cvt_hilo(b, hb, lb);
    __nv_bfloat162 H; H.x = ha; H.y = hb;
    __nv_bfloat162 L; L.x = la; L.y = lb;
    hi = *reinterpret_cast<uint32_t*>(&H);
    lo = *reinterpret_cast<uint32_t*>(&L);
}

// ---------------------------------------------------------------------------
__global__ __launch_bounds__(256) void cvt_qkv(
    const float* __restrict__ q, const float* __restrict__ k,
    const float* __restrict__ v,
    __nv_bfloat16* __restrict__ hp, __nv_bfloat16* __restrict__ lp)
{
    const int z = blockIdx.z;
    const float* x = (z == 0) ? q : (z == 1) ? k : v;
    const int i = blockIdx.x * 256 + threadIdx.x;
    float4 val = reinterpret_cast<const float4*>(x)[i];
    __nv_bfloat16 h[4], l[4];
    cvt_hilo(val.x, h[0], l[0]);
    cvt_hilo(val.y, h[1], l[1]);
    cvt_hilo(val.z, h[2], l[2]);
    cvt_hilo(val.w, h[3], l[3]);
    reinterpret_cast<uint2*>(hp + (size_t)z * LNE)[i] = *reinterpret_cast<uint2*>(h);
    reinterpret_cast<uint2*>(lp + (size_t)z * LNE)[i] = *reinterpret_cast<uint2*>(l);
}

__global__ __launch_bounds__(256) void cvt_planes(
    const float* __restrict__ x,
    __nv_bfloat16* __restrict__ hp, __nv_bfloat16* __restrict__ lp, int n4)
{
    const int i = blockIdx.x * 256 + threadIdx.x;
    if (i >= n4) return;
    float4 v = reinterpret_cast<const float4*>(x)[i];
    __nv_bfloat16 h[4], l[4];
    cvt_hilo(v.x, h[0], l[0]);
    cvt_hilo(v.y, h[1], l[1]);
    cvt_hilo(v.z, h[2], l[2]);
    cvt_hilo(v.w, h[3], l[3]);
    reinterpret_cast<uint2*>(hp)[i] = *reinterpret_cast<uint2*>(h);
    reinterpret_cast<uint2*>(lp)[i] = *reinterpret_cast<uint2*>(l);
}

// ---------------------------------------------------------------------------
// GEMM (bf16 hi/lo 3-term, cp.async double-buffered, grid.z batched).
// MODE 0: fp32 C. MODE 1: bf16 hi/lo planes out, q-scale on z==0.
// __launch_bounds__(256, 3): cap regs at 85 so 3 CTAs/SM fit (occupancy).
// ---------------------------------------------------------------------------
constexpr int BM = 128, BN = 64, BK = 32, LDS_ = BK + 8;  // 40
constexpr int ABUF = BM * LDS_ * 2;
constexpr int BBUF = BN * LDS_ * 2;
constexpr int OFF_AH = 0;
constexpr int OFF_AL = 2 * ABUF;
constexpr int OFF_BH = 4 * ABUF;
constexpr int OFF_BL = OFF_BH + 2 * BBUF;
constexpr int SMEM_GEMM = OFF_BL + 2 * BBUF;   // 61440

template <int MODE>
__global__ __launch_bounds__(256, 3) void gemm_bf16(
    const __nv_bfloat16* __restrict__ Ab,
    const __nv_bfloat16* __restrict__ Alb,
    const __nv_bfloat16* __restrict__ Wb,
    const __nv_bfloat16* __restrict__ Wlb,
    const float* __restrict__ bb,
    float* __restrict__ Cf,
    __nv_bfloat16* __restrict__ Chp,
    __nv_bfloat16* __restrict__ Clp)
{
    extern __shared__ char dsm[];
    const uint32_t sbase = smem_u32(dsm);

    const int z = blockIdx.z;
    const __nv_bfloat16* Ahg = Ab  + (size_t)z * LNE;
    const __nv_bfloat16* Alg = Alb + (size_t)z * LNE;
    const __nv_bfloat16* Whg = Wb  + (size_t)z * EE * EE;
    const __nv_bfloat16* Wlg = Wlb + (size_t)z * EE * EE;
    const float* bias = bb + z * EE;

    const int tid  = threadIdx.x;
    const int lane = tid & 31;
    const int wid  = tid >> 5;
    const int wm   = wid & 3;
    const int wn   = wid >> 2;
    const int grp  = lane >> 2;
    const int tig  = lane & 3;
    const int m0   = blockIdx.y * BM;
    const int n0   = blockIdx.x * BN;

    float acc[2][4][4];
#pragma unroll
    for (int mt = 0; mt < 2; mt++)
#pragma unroll
        for (int nt = 0; nt < 4; nt++)
#pragma unroll
            for (int i = 0; i < 4; i++) acc[mt][nt][i] = 0.0f;

    const int a_row_l = lane & 15;
    const int a_col_l = (lane >> 4) * 8;
    const int b_row_l = (lane & 7) + ((lane >> 4) << 3);
    const int b_col_l = ((lane >> 3) & 1) * 8;

    const int sa_row = tid >> 2;
    const int sa_kc  = (tid & 3) * 8;

    auto stage = [&](int buf, int k0) {
#pragma unroll
        for (int p = 0; p < 2; p++) {
            const int row = sa_row + p * 64;
            const size_t g = (size_t)(m0 + row) * EE + k0 + sa_kc;
            const uint32_t s = sbase + OFF_AH + buf * ABUF + row * (LDS_ * 2) + sa_kc * 2;
            cpasync16(s, Ahg + g);
            cpasync16(s + (OFF_AL - OFF_AH), Alg + g);
        }
        {
            const size_t g = (size_t)(n0 + sa_row) * EE + k0 + sa_kc;
            const uint32_t s = sbase + OFF_BH + buf * BBUF + sa_row * (LDS_ * 2) + sa_kc * 2;
            cpasync16(s, Whg + g);
            cpasync16(s + (OFF_BL - OFF_BH), Wlg + g);
        }
        asm volatile("cp.async.commit_group;");
    };

    stage(0, 0);
    constexpr int NCH = EE / BK;
#pragma unroll 1
    for (int ch = 0; ch < NCH; ch++) {
        if (ch < NCH - 1) {
            stage((ch + 1) & 1, (ch + 1) * BK);
            asm volatile("cp.async.wait_group 1;");
        } else {
            asm volatile("cp.async.wait_group 0;");
        }
        __syncthreads();

        const int buf = ch & 1;
        const uint32_t sAh = sbase + OFF_AH + buf * ABUF;
        const uint32_t sAl = sbase + OFF_AL + buf * ABUF;
        const uint32_t sBh = sbase + OFF_BH + buf * BBUF;
        const uint32_t sBl = sbase + OFF_BL + buf * BBUF;

#pragma unroll
        for (int ks = 0; ks < 2; ks++) {
            const int kb = ks * 16;
            uint32_t ah[2][4], al[2][4];
#pragma unroll
            for (int mt = 0; mt < 2; mt++) {
                const uint32_t aoff =
                    ((wm * 32 + mt * 16 + a_row_l) * LDS_ + kb + a_col_l) * 2;
                ldmx4(ah[mt], sAh + aoff);
                ldmx4(al[mt], sAl + aoff);
            }
#pragma unroll
            for (int ntp = 0; ntp < 2; ntp++) {
                const uint32_t boff =
                    ((wn * 32 + ntp * 16 + b_row_l) * LDS_ + kb + b_col_l) * 2;
                uint32_t bh[4], bl[4];
                ldmx4(bh, sBh + boff);
                ldmx4(bl, sBl + boff);
#pragma unroll
                for (int j = 0; j < 2; j++) {
                    const int nt = ntp * 2 + j;
                    const uint32_t b0h = bh[2 * j], b1h = bh[2 * j + 1];
                    const uint32_t b0l = bl[2 * j], b1l = bl[2 * j + 1];
#pragma unroll
                    for (int mt = 0; mt < 2; mt++) {
                        mma_bf16(acc[mt][nt], ah[mt][0], ah[mt][1], ah[mt][2], ah[mt][3], b0h, b1h);
                        mma_bf16(acc[mt][nt], ah[mt][0], ah[mt][1], ah[mt][2], ah[mt][3], b0l, b1l);
                        mma_bf16(acc[mt][nt], al[mt][0], al[mt][1], al[mt][2], al[mt][3], b0h, b1h);
                    }
                }
            }
        }
        __syncthreads();
    }

    if (MODE == 0) {
        float* C = Cf;
#pragma unroll
        for (int mt = 0; mt < 2; mt++) {
            const int r0 = m0 + wm * 32 + mt * 16 + grp;
#pragma unroll
            for (int nt = 0; nt < 4; nt++) {
                const int c = n0 + wn * 32 + nt * 8 + 2 * tig;
                const float b0v = bias[c], b1v = bias[c + 1];
                float2 o0 = make_float2(acc[mt][nt][0] + b0v, acc[mt][nt][1] + b1v);
                float2 o1 = make_float2(acc[mt][nt][2] + b0v, acc[mt][nt][3] + b1v);
                *reinterpret_cast<float2*>(&C[(size_t)r0 * EE + c]) = o0;
                *reinterpret_cast<float2*>(&C[(size_t)(r0 + 8) * EE + c]) = o1;
            }
        }
    } else {
        const float sc = (z == 0) ? QSCALE : 1.0f;
        __nv_bfloat16* Ch = Chp + (size_t)z * LNE;
        __nv_bfloat16* Cl = Clp + (size_t)z * LNE;
#pragma unroll
        for (int mt = 0; mt < 2; mt++) {
            const int r0 = m0 + wm * 32 + mt * 16 + grp;
#pragma unroll
            for (int nt = 0; nt < 4; nt++) {
                const int c = n0 + wn * 32 + nt * 8 + 2 * tig;
                const float b0v = bias[c], b1v = bias[c + 1];
                uint32_t hi0, lo0, hi1, lo1;
                pack2((acc[mt][nt][0] + b0v) * sc, (acc[mt][nt][1] + b1v) * sc, hi0, lo0);
                pack2((acc[mt][nt][2] + b0v) * sc, (acc[mt][nt][3] + b1v) * sc, hi1, lo1);
                *reinterpret_cast<uint32_t*>(&Ch[(size_t)r0 * EE + c]) = hi0;
                *reinterpret_cast<uint32_t*>(&Cl[(size_t)r0 * EE + c]) = lo0;
                *reinterpret_cast<uint32_t*>(&Ch[(size_t)(r0 + 8) * EE + c]) = hi1;
                *reinterpret_cast<uint32_t*>(&Cl[(size_t)(r0 + 8) * EE + c]) = lo1;
            }
        }
    }
}

// ---------------------------------------------------------------------------
// MMA sliding-window attention (unchanged math from R10).
// ---------------------------------------------------------------------------
constexpr int TLQ = 64, KR = 96;
constexpr int KSTR = 40;
constexpr int PSTR = 104;
constexpr int AOFF_QH = 0;
constexpr int AOFF_QL = AOFF_QH + TLQ * KSTR * 2;
constexpr int AOFF_KH = AOFF_QL + TLQ * KSTR * 2;
constexpr int AOFF_KL = AOFF_KH + KR * KSTR * 2;
constexpr int AOFF_VH = AOFF_KL + KR * KSTR * 2;
constexpr int AOFF_VL = AOFF_VH + KR * KSTR * 2;
constexpr int AOFF_PH = AOFF_VL + KR * KSTR * 2;
constexpr int AOFF_PL = AOFF_PH + TLQ * PSTR * 2;
constexpr int AOFF_DEN = AOFF_PL + TLQ * PSTR * 2;
constexpr int SMEM_ATTN = AOFF_DEN + TLQ * 2 * 4;   // 68096

__global__ __launch_bounds__(256, 3) void attn_mma(
    const __nv_bfloat16* __restrict__ qh, const __nv_bfloat16* __restrict__ ql,
    const __nv_bfloat16* __restrict__ kh, const __nv_bfloat16* __restrict__ kl,
    const __nv_bfloat16* __restrict__ vh, const __nv_bfloat16* __restrict__ vl,
    __nv_bfloat16* __restrict__ oh, __nv_bfloat16* __restrict__ ol)
{
    extern __shared__ char dsm[];
    const uint32_t sb = smem_u32(dsm);

    const int nhid = blockIdx.y;
    const int n    = nhid / HH;
    const int h    = nhid % HH;
    const int l0   = blockIdx.x * TLQ;
    const int tid  = threadIdx.x;
    const int lane = tid & 31;
    const int wid  = tid >> 5;
    const int mt   = wid & 3;
    const int nhf  = wid >> 2;
    const int grp  = lane >> 2;
    const int tig  = lane & 3;

    {
        const int row = tid >> 2, ch = tid & 3;
        const size_t src = ((size_t)(l0 + row) * NB + n) * EE + h * HD + ch * 8;
        const uint32_t dst = sb + AOFF_QH + row * (KSTR * 2) + ch * 16;
        cpasync16(dst, qh + src);
        cpasync16(dst + (AOFF_QL - AOFF_QH), ql + src);
    }
#pragma unroll
    for (int i = 0; i < 2; i++) {
        const int idx = tid + i * 256;
        if (idx < KR * 4) {
            const int row = idx >> 2, ch = idx & 3;
            const int gl = l0 - 32 + row;
            const uint32_t dk = sb + AOFF_KH + row * (KSTR * 2) + ch * 16;
            const uint32_t dv = sb + AOFF_VH + row * (KSTR * 2) + ch * 16;
            if (gl >= 0) {
                const size_t src = ((size_t)gl * NB + n) * EE + h * HD + ch * 8;
                cpasync16(dk, kh + src);
                cpasync16(dk + (AOFF_KL - AOFF_KH), kl + src);
                cpasync16(dv, vh + src);
                cpasync16(dv + (AOFF_VL - AOFF_VH), vl + src);
            } else {
                const uint4 z4 = make_uint4(0, 0, 0, 0);
                const int bo = row * (KSTR * 2) + ch * 16;
                *reinterpret_cast<uint4*>(dsm + AOFF_KH + bo) = z4;
                *reinterpret_cast<uint4*>(dsm + AOFF_KL + bo) = z4;
                *reinterpret_cast<uint4*>(dsm + AOFF_VH + bo) = z4;
                *reinterpret_cast<uint4*>(dsm + AOFF_VL + bo) = z4;
            }
        }
    }
    asm volatile("cp.async.commit_group;");
    asm volatile("cp.async.wait_group 0;");
    __syncthreads();

    const int a_row_l = lane & 15;
    const int a_col_l = (lane >> 4) * 8;
    const int b_row_l = (lane & 7) + ((lane >> 4) << 3);
    const int b_col_l = ((lane >> 3) & 1) * 8;

    float scacc[6][4];
#pragma unroll
    for (int t = 0; t < 6; t++)
#pragma unroll
        for (int i = 0; i < 4; i++) scacc[t][i] = 0.0f;

#pragma unroll
    for (int ks = 0; ks < 2; ks++) {
        const int kb = ks * 16;
        uint32_t qa[4], qb[4];
        const uint32_t aoff = (mt * 16 + a_row_l) * (KSTR * 2) + (kb + a_col_l) * 2;
        ldmx4(qa, sb + AOFF_QH + aoff);
        ldmx4(qb, sb + AOFF_QL + aoff);
#pragma unroll
        for (int p = 0; p < 3; p++) {
            const int nb = nhf * 48 + p * 16;
            const uint32_t boff = (nb + b_row_l) * (KSTR * 2) + (kb + b_col_l) * 2;
            uint32_t kbh[4], kbl[4];
            ldmx4(kbh, sb + AOFF_KH + boff);
            ldmx4(kbl, sb + AOFF_KL + boff);
#pragma unroll
            for (int j = 0; j < 2; j++) {
                const int t = p * 2 + j;
                mma_bf16(scacc[t], qa[0], qa[1], qa[2], qa[3], kbh[2 * j], kbh[2 * j + 1]);
                mma_bf16(scacc[t], qa[0], qa[1], qa[2], qa[3], kbl[2 * j], kbl[2 * j + 1]);
                mma_bf16(scacc[t], qb[0], qb[1], qb[2], qb[3], kbh[2 * j], kbh[2 * j + 1]);
            }
        }
    }

    const int r0 = mt * 16 + grp;
    const int r1 = r0 + 8;
    float sA = 0.0f, sB = 0.0f;
#pragma unroll
    for (int t = 0; t < 6; t++) {
        const int c0 = nhf * 48 + t * 8 + 2 * tig;
        const int c1 = c0 + 1;
        const float m00 = (c0 >= r0 && c0 <= r0 + 32 && l0 + c0 >= 32) ? 0.0f : NEG;
        const float m01 = (c1 >= r0 && c1 <= r0 + 32 && l0 + c1 >= 32) ? 0.0f : NEG;
        const float m10 = (c0 >= r1 && c0 <= r1 + 32 && l0 + c0 >= 32) ? 0.0f : NEG;
        const float m11 = (c1 >= r1 && c1 <= r1 + 32 && l0 + c1 >= 32) ? 0.0f : NEG;
        const float e00 = __expf(scacc[t][0] + m00);
        const float e01 = __expf(scacc[t][1] + m01);
        const float e10 = __expf(scacc[t][2] + m10);
        const float e11 = __expf(scacc[t][3] + m11);
        sA += e00 + e01;
        sB += e10 + e11;
        uint32_t hi0, lo0, hi1, lo1;
        pack2(e00, e01, hi0, lo0);
        pack2(e10, e11, hi1, lo1);
        const int bo0 = (r0 * PSTR + c0) * 2;
        const int bo1 = (r1 * PSTR + c0) * 2;
        *reinterpret_cast<uint32_t*>(dsm + AOFF_PH + bo0) = hi0;
        *reinterpret_cast<uint32_t*>(dsm + AOFF_PL + bo0) = lo0;
        *reinterpret_cast<uint32_t*>(dsm + AOFF_PH + bo1) = hi1;
        *reinterpret_cast<uint32_t*>(dsm + AOFF_PL + bo1) = lo1;
    }
    sA += __shfl_xor_sync(0xFFFFFFFFu, sA, 1);
    sA += __shfl_xor_sync(0xFFFFFFFFu, sA, 2);
    sB += __shfl_xor_sync(0xFFFFFFFFu, sB, 1);
    sB += __shfl_xor_sync(0xFFFFFFFFu, sB, 2);
    if (tig == 0) {
        *reinterpret_cast<float*>(dsm + AOFF_DEN + (r0 * 2 + nhf) * 4) = sA;
        *reinterpret_cast<float*>(dsm + AOFF_DEN + (r1 * 2 + nhf) * 4) = sB;
    }
    __syncthreads();

    float oacc[2][4];
#pragma unroll
    for (int j = 0; j < 2; j++)
#pragma unroll
        for (int i = 0; i < 4; i++) oacc[j][i] = 0.0f;

#pragma unroll
    for (int ks = 0; ks < 6; ks++) {
        const int kb = ks * 16;
        uint32_t pa[4], pb[4];
        const uint32_t aoff = (mt * 16 + a_row_l) * (PSTR * 2) + (kb + a_col_l) * 2;
        ldmx4(pa, sb + AOFF_PH + aoff);
        ldmx4(pb, sb + AOFF_PL + aoff);
        const uint32_t voff = (kb + a_row_l) * (KSTR * 2) + nhf * 32 + (lane >> 4) * 16;
        uint32_t vth[4], vtl[4];
        ldmx4t(vth, sb + AOFF_VH + voff);
        ldmx4t(vtl, sb + AOFF_VL + voff);
#pragma unroll
        for (int j = 0; j < 2; j++) {
            mma_bf16(oacc[j], pa[0], pa[1], pa[2], pa[3], vth[2 * j], vth[2 * j + 1]);
            mma_bf16(oacc[j], pa[0], pa[1], pa[2], pa[3], vtl[2 * j], vtl[2 * j + 1]);
            mma_bf16(oacc[j], pb[0], pb[1], pb[2], pb[3], vth[2 * j], vth[2 * j + 1]);
        }
    }

    const float dA = *reinterpret_cast<float*>(dsm + AOFF_DEN + r0 * 8) +
                     *reinterpret_cast<float*>(dsm + AOFF_DEN + r0 * 8 + 4);
    const float dB = *reinterpret_cast<float*>(dsm + AOFF_DEN + r1 * 8) +
                     *reinterpret_cast<float*>(dsm + AOFF_DEN + r1 * 8 + 4);
    const float invA = 1.0f / dA;
    const float invB = 1.0f / dB;
    const size_t base0 = ((size_t)(l0 + r0) * NB + n) * EE + h * HD;
    const size_t base1 = ((size_t)(l0 + r1) * NB + n) * EE + h * HD;
#pragma unroll
    for (int j = 0; j < 2; j++) {
        const int d0 = nhf * 16 + j * 8 + 2 * tig;
        uint32_t hi0, lo0, hi1, lo1;
        pack2(oacc[j][0] * invA, oacc[j][1] * invA, hi0, lo0);
        pack2(oacc[j][2] * invB, oacc[j][3] * invB, hi1, lo1);
        *reinterpret_cast<uint32_t*>(oh + base0 + d0) = hi0;
        *reinterpret_cast<uint32_t*>(ol + base0 + d0) = lo0;
        *reinterpret_cast<uint32_t*>(oh + base1 + d0) = hi1;
        *reinterpret_cast<uint32_t*>(ol + base1 + d0) = lo1;
    }
}

// ---------------------------------------------------------------------------
extern "C" void kernel_launch(void* const* d_in, const int* in_sizes, int n_in,
                              void* d_out, int out_size)
{
    const float* query = (const float*)d_in[0];
    const float* key   = (const float*)d_in[1];
    const float* value = (const float*)d_in[2];
    const float* w_in  = (const float*)d_in[3];
    const float* b_in  = (const float*)d_in[4];
    const float* w_out = (const float*)d_in[5];
    const float* b_out = (const float*)d_in[6];
    float* out = (float*)d_out;

    __nv_bfloat16 *inh = nullptr, *inl = nullptr, *hi = nullptr, *lo = nullptr;
    __nv_bfloat16 *wh = nullptr, *wl = nullptr;
    cudaGetSymbolAddress((void**)&inh, g_inh);
    cudaGetSymbolAddress((void**)&inl, g_inl);
    cudaGetSymbolAddress((void**)&hi,  g_hi);
    cudaGetSymbolAddress((void**)&lo,  g_lo);
    cudaGetSymbolAddress((void**)&wh,  g_wh);
    cudaGetSymbolAddress((void**)&wl,  g_wl);

    __nv_bfloat16 *wih = wh, *wil = wl;
    __nv_bfloat16 *woh = wh + 768 * 256, *wol = wl + 768 * 256;
    __nv_bfloat16 *ohp = hi + 3 * (size_t)LNE, *olp = lo + 3 * (size_t)LNE;

    cudaFuncSetAttribute(gemm_bf16<0>,
        cudaFuncAttributeMaxDynamicSharedMemorySize, SMEM_GEMM);
    cudaFuncSetAttribute(gemm_bf16<1>,
        cudaFuncAttributeMaxDynamicSharedMemorySize, SMEM_GEMM);
    cudaFuncSetAttribute(attn_mma,
        cudaFuncAttributeMaxDynamicSharedMemorySize, SMEM_ATTN);

    cvt_qkv<<<dim3(LNE / 4 / 256, 1, 3), 256>>>(query, key, value, inh, inl);
    const int w4a = 768 * 256 / 4, w4b = 256 * 256 / 4;
    cvt_planes<<<(w4a + 255) / 256, 256>>>(w_in,  wih, wil, w4a);
    cvt_planes<<<(w4b + 255) / 256, 256>>>(w_out, woh, wol, w4b);

    gemm_bf16<1><<<dim3(EE / BN, M / BM, 3), 256, SMEM_GEMM>>>(
        inh, inl, wih, wil, b_in, nullptr, hi, lo);

    attn_mma<<<dim3(LL / TLQ, NB * HH), 256, SMEM_ATTN>>>(
        hi, lo, hi + LNE, lo + LNE, hi + 2 * (size_t)LNE, lo + 2 * (size_t)LNE,
        ohp, olp);

    gemm_bf16<0><<<dim3(EE / BN, M / BM, 1), 256, SMEM_GEMM>>>(
        ohp, olp, woh, wol, b_out, out, nullptr, nullptr);
}

// round 13
// speedup vs baseline: 2.7469x; 1.0400x over previous
#include <cuda_runtime.h>
#include <cuda_bf16.h>
#include <math.h>
#include <stdint.h>

// Problem constants
constexpr int LL   = 8192;
constexpr int NB   = 2;
constexpr int EE   = 256;
constexpr int HH   = 8;
constexpr int HD   = 32;
constexpr int M    = LL * NB;     // 16384
constexpr int LNE  = M * EE;
constexpr int W4A  = 768 * 256 / 4;   // float4 count of w_in
constexpr int W4B  = 256 * 256 / 4;   // float4 count of w_out
constexpr float NEG = -1000000000.0f;
constexpr float QSCALE = 0.17677669529663687f;  // 1/sqrt(32)

// Scratch planes
__device__ __align__(16) __nv_bfloat16 g_inh[3 * LNE];
__device__ __align__(16) __nv_bfloat16 g_inl[3 * LNE];
__device__ __align__(16) __nv_bfloat16 g_hi[4 * LNE];
__device__ __align__(16) __nv_bfloat16 g_lo[4 * LNE];
__device__ __align__(16) __nv_bfloat16 g_wh[(W4A + W4B) * 4];
__device__ __align__(16) __nv_bfloat16 g_wl[(W4A + W4B) * 4];

// ---------------------------------------------------------------------------
__device__ __forceinline__ void mma_bf16(float* c,
    uint32_t a0, uint32_t a1, uint32_t a2, uint32_t a3,
    uint32_t b0, uint32_t b1)
{
    asm volatile(
        "mma.sync.aligned.m16n8k16.row.col.f32.bf16.bf16.f32 "
        "{%0,%1,%2,%3}, {%4,%5,%6,%7}, {%8,%9}, {%0,%1,%2,%3};"
        : "+f"(c[0]), "+f"(c[1]), "+f"(c[2]), "+f"(c[3])
        : "r"(a0), "r"(a1), "r"(a2), "r"(a3), "r"(b0), "r"(b1));
}
__device__ __forceinline__ void ldmx4(uint32_t* r, uint32_t addr) {
    asm volatile("ldmatrix.sync.aligned.m8n8.x4.shared.b16 {%0,%1,%2,%3}, [%4];"
        : "=r"(r[0]), "=r"(r[1]), "=r"(r[2]), "=r"(r[3]) : "r"(addr));
}
__device__ __forceinline__ void ldmx4t(uint32_t* r, uint32_t addr) {
    asm volatile("ldmatrix.sync.aligned.m8n8.x4.trans.shared.b16 {%0,%1,%2,%3}, [%4];"
        : "=r"(r[0]), "=r"(r[1]), "=r"(r[2]), "=r"(r[3]) : "r"(addr));
}
__device__ __forceinline__ uint32_t smem_u32(const void* p) {
    uint32_t a;
    asm("{ .reg .u64 t; cvta.to.shared.u64 t, %1; cvt.u32.u64 %0, t; }"
        : "=r"(a) : "l"(p));
    return a;
}
__device__ __forceinline__ void cpasync16(uint32_t s, const void* g) {
    asm volatile("cp.async.cg.shared.global [%0], [%1], 16;" :: "r"(s), "l"(g));
}
__device__ __forceinline__ void cvt_hilo(float x, __nv_bfloat16& h, __nv_bfloat16& l) {
    h = __float2bfloat16_rn(x);
    l = __float2bfloat16_rn(x - __bfloat162float(h));
}
__device__ __forceinline__ void pack2(float a, float b, uint32_t& hi, uint32_t& lo) {
    __nv_bfloat16 ha, la, hb, lb;
    cvt_hilo(a, ha, la);
    cvt_hilo(b, hb, lb);
    __nv_bfloat162 H; H.x = ha; H.y = hb;
    __nv_bfloat162 L; L.x = la; L.y = lb;
    hi = *reinterpret_cast<uint32_t*>(&H);
    lo = *reinterpret_cast<uint32_t*>(&L);
}

// ---------------------------------------------------------------------------
__global__ __launch_bounds__(256) void cvt_qkv(
    const float* __restrict__ q, const float* __restrict__ k,
    const float* __restrict__ v,
    __nv_bfloat16* __restrict__ hp, __nv_bfloat16* __restrict__ lp)
{
    const int z = blockIdx.z;
    const float* x = (z == 0) ? q : (z == 1) ? k : v;
    const int i = blockIdx.x * 256 + threadIdx.x;
    float4 val = reinterpret_cast<const float4*>(x)[i];
    __nv_bfloat16 h[4], l[4];
    cvt_hilo(val.x, h[0], l[0]);
    cvt_hilo(val.y, h[1], l[1]);
    cvt_hilo(val.z, h[2], l[2]);
    cvt_hilo(val.w, h[3], l[3]);
    reinterpret_cast<uint2*>(hp + (size_t)z * LNE)[i] = *reinterpret_cast<uint2*>(h);
    reinterpret_cast<uint2*>(lp + (size_t)z * LNE)[i] = *reinterpret_cast<uint2*>(l);
}

// Merged weight conversion: w_in (49152 float4) then w_out (16384 float4).
__global__ __launch_bounds__(256) void cvt_w(
    const float* __restrict__ w_in, const float* __restrict__ w_out,
    __nv_bfloat16* __restrict__ hp, __nv_bfloat16* __restrict__ lp)
{
    const int i = blockIdx.x * 256 + threadIdx.x;  // exact: (W4A+W4B)/256 blocks
    float4 v = (i < W4A) ? reinterpret_cast<const float4*>(w_in)[i]
                         : reinterpret_cast<const float4*>(w_out)[i - W4A];
    __nv_bfloat16 h[4], l[4];
    cvt_hilo(v.x, h[0], l[0]);
    cvt_hilo(v.y, h[1], l[1]);
    cvt_hilo(v.z, h[2], l[2]);
    cvt_hilo(v.w, h[3], l[3]);
    reinterpret_cast<uint2*>(hp)[i] = *reinterpret_cast<uint2*>(h);
    reinterpret_cast<uint2*>(lp)[i] = *reinterpret_cast<uint2*>(l);
}

// ---------------------------------------------------------------------------
// GEMM (unchanged from R11: bf16 hi/lo 3-term, cp.async double-buffered,
// grid.z batched, at the mma.sync throughput ceiling).
// ---------------------------------------------------------------------------
constexpr int BM = 128, BN = 64, BK = 32, LDS_ = BK + 8;  // 40
constexpr int ABUF = BM * LDS_ * 2;
constexpr int BBUF = BN * LDS_ * 2;
constexpr int OFF_AH = 0;
constexpr int OFF_AL = 2 * ABUF;
constexpr int OFF_BH = 4 * ABUF;
constexpr int OFF_BL = OFF_BH + 2 * BBUF;
constexpr int SMEM_GEMM = OFF_BL + 2 * BBUF;   // 61440

template <int MODE>
__global__ __launch_bounds__(256, 3) void gemm_bf16(
    const __nv_bfloat16* __restrict__ Ab,
    const __nv_bfloat16* __restrict__ Alb,
    const __nv_bfloat16* __restrict__ Wb,
    const __nv_bfloat16* __restrict__ Wlb,
    const float* __restrict__ bb,
    float* __restrict__ Cf,
    __nv_bfloat16* __restrict__ Chp,
    __nv_bfloat16* __restrict__ Clp)
{
    extern __shared__ char dsm[];
    const uint32_t sbase = smem_u32(dsm);

    const int z = blockIdx.z;
    const __nv_bfloat16* Ahg = Ab  + (size_t)z * LNE;
    const __nv_bfloat16* Alg = Alb + (size_t)z * LNE;
    const __nv_bfloat16* Whg = Wb  + (size_t)z * EE * EE;
    const __nv_bfloat16* Wlg = Wlb + (size_t)z * EE * EE;
    const float* bias = bb + z * EE;

    const int tid  = threadIdx.x;
    const int lane = tid & 31;
    const int wid  = tid >> 5;
    const int wm   = wid & 3;
    const int wn   = wid >> 2;
    const int grp  = lane >> 2;
    const int tig  = lane & 3;
    const int m0   = blockIdx.y * BM;
    const int n0   = blockIdx.x * BN;

    float acc[2][4][4];
#pragma unroll
    for (int mt = 0; mt < 2; mt++)
#pragma unroll
        for (int nt = 0; nt < 4; nt++)
#pragma unroll
            for (int i = 0; i < 4; i++) acc[mt][nt][i] = 0.0f;

    const int a_row_l = lane & 15;
    const int a_col_l = (lane >> 4) * 8;
    const int b_row_l = (lane & 7) + ((lane >> 4) << 3);
    const int b_col_l = ((lane >> 3) & 1) * 8;

    const int sa_row = tid >> 2;
    const int sa_kc  = (tid & 3) * 8;

    auto stage = [&](int buf, int k0) {
#pragma unroll
        for (int p = 0; p < 2; p++) {
            const int row = sa_row + p * 64;
            const size_t g = (size_t)(m0 + row) * EE + k0 + sa_kc;
            const uint32_t s = sbase + OFF_AH + buf * ABUF + row * (LDS_ * 2) + sa_kc * 2;
            cpasync16(s, Ahg + g);
            cpasync16(s + (OFF_AL - OFF_AH), Alg + g);
        }
        {
            const size_t g = (size_t)(n0 + sa_row) * EE + k0 + sa_kc;
            const uint32_t s = sbase + OFF_BH + buf * BBUF + sa_row * (LDS_ * 2) + sa_kc * 2;
            cpasync16(s, Whg + g);
            cpasync16(s + (OFF_BL - OFF_BH), Wlg + g);
        }
        asm volatile("cp.async.commit_group;");
    };

    stage(0, 0);
    constexpr int NCH = EE / BK;
#pragma unroll 1
    for (int ch = 0; ch < NCH; ch++) {
        if (ch < NCH - 1) {
            stage((ch + 1) & 1, (ch + 1) * BK);
            asm volatile("cp.async.wait_group 1;");
        } else {
            asm volatile("cp.async.wait_group 0;");
        }
        __syncthreads();

        const int buf = ch & 1;
        const uint32_t sAh = sbase + OFF_AH + buf * ABUF;
        const uint32_t sAl = sbase + OFF_AL + buf * ABUF;
        const uint32_t sBh = sbase + OFF_BH + buf * BBUF;
        const uint32_t sBl = sbase + OFF_BL + buf * BBUF;

#pragma unroll
        for (int ks = 0; ks < 2; ks++) {
            const int kb = ks * 16;
            uint32_t ah[2][4], al[2][4];
#pragma unroll
            for (int mt = 0; mt < 2; mt++) {
                const uint32_t aoff =
                    ((wm * 32 + mt * 16 + a_row_l) * LDS_ + kb + a_col_l) * 2;
                ldmx4(ah[mt], sAh + aoff);
                ldmx4(al[mt], sAl + aoff);
            }
#pragma unroll
            for (int ntp = 0; ntp < 2; ntp++) {
                const uint32_t boff =
                    ((wn * 32 + ntp * 16 + b_row_l) * LDS_ + kb + b_col_l) * 2;
                uint32_t bh[4], bl[4];
                ldmx4(bh, sBh + boff);
                ldmx4(bl, sBl + boff);
#pragma unroll
                for (int j = 0; j < 2; j++) {
                    const int nt = ntp * 2 + j;
                    const uint32_t b0h = bh[2 * j], b1h = bh[2 * j + 1];
                    const uint32_t b0l = bl[2 * j], b1l = bl[2 * j + 1];
#pragma unroll
                    for (int mt = 0; mt < 2; mt++) {
                        mma_bf16(acc[mt][nt], ah[mt][0], ah[mt][1], ah[mt][2], ah[mt][3], b0h, b1h);
                        mma_bf16(acc[mt][nt], ah[mt][0], ah[mt][1], ah[mt][2], ah[mt][3], b0l, b1l);
                        mma_bf16(acc[mt][nt], al[mt][0], al[mt][1], al[mt][2], al[mt][3], b0h, b1h);
                    }
                }
            }
        }
        __syncthreads();
    }

    if (MODE == 0) {
        float* C = Cf;
#pragma unroll
        for (int mt = 0; mt < 2; mt++) {
            const int r0 = m0 + wm * 32 + mt * 16 + grp;
#pragma unroll
            for (int nt = 0; nt < 4; nt++) {
                const int c = n0 + wn * 32 + nt * 8 + 2 * tig;
                const float b0v = bias[c], b1v = bias[c + 1];
                float2 o0 = make_float2(acc[mt][nt][0] + b0v, acc[mt][nt][1] + b1v);
                float2 o1 = make_float2(acc[mt][nt][2] + b0v, acc[mt][nt][3] + b1v);
                *reinterpret_cast<float2*>(&C[(size_t)r0 * EE + c]) = o0;
                *reinterpret_cast<float2*>(&C[(size_t)(r0 + 8) * EE + c]) = o1;
            }
        }
    } else {
        const float sc = (z == 0) ? QSCALE : 1.0f;
        __nv_bfloat16* Ch = Chp + (size_t)z * LNE;
        __nv_bfloat16* Cl = Clp + (size_t)z * LNE;
#pragma unroll
        for (int mt = 0; mt < 2; mt++) {
            const int r0 = m0 + wm * 32 + mt * 16 + grp;
#pragma unroll
            for (int nt = 0; nt < 4; nt++) {
                const int c = n0 + wn * 32 + nt * 8 + 2 * tig;
                const float b0v = bias[c], b1v = bias[c + 1];
                uint32_t hi0, lo0, hi1, lo1;
                pack2((acc[mt][nt][0] + b0v) * sc, (acc[mt][nt][1] + b1v) * sc, hi0, lo0);
                pack2((acc[mt][nt][2] + b0v) * sc, (acc[mt][nt][3] + b1v) * sc, hi1, lo1);
                *reinterpret_cast<uint32_t*>(&Ch[(size_t)r0 * EE + c]) = hi0;
                *reinterpret_cast<uint32_t*>(&Cl[(size_t)r0 * EE + c]) = lo0;
                *reinterpret_cast<uint32_t*>(&Ch[(size_t)(r0 + 8) * EE + c]) = hi1;
                *reinterpret_cast<uint32_t*>(&Cl[(size_t)(r0 + 8) * EE + c]) = lo1;
            }
        }
    }
}

// ---------------------------------------------------------------------------
// Banded MMA sliding-window attention.
// Query band structure: rows [16mt, 16mt+16) only touch key cols
// [16mt, 16mt+48) of the 96-col K tile. Scores + P*V restricted to the band:
// halves the MMA count vs full 64x96.
// Warp (mt, nhf): scores — nhf takes band cols {nhf*16..+16} U {32+nhf*8..+8};
// output — nhf takes dims [nhf*16, +16) over the full 48-deep band.
// ---------------------------------------------------------------------------
constexpr int TLQ = 64, KR = 96;
constexpr int KSTR = 40;
constexpr int PSTR = 56;    // banded P: 48 cols + 8 pad
constexpr int AOFF_QH = 0;
constexpr int AOFF_QL = AOFF_QH + TLQ * KSTR * 2;   // 5120
constexpr int AOFF_KH = AOFF_QL + TLQ * KSTR * 2;   // 10240
constexpr int AOFF_KL = AOFF_KH + KR * KSTR * 2;    // 17920
constexpr int AOFF_VH = AOFF_KL + KR * KSTR * 2;    // 25600
constexpr int AOFF_VL = AOFF_VH + KR * KSTR * 2;    // 33280
constexpr int AOFF_PH = AOFF_VL + KR * KSTR * 2;    // 40960
constexpr int AOFF_PL = AOFF_PH + TLQ * PSTR * 2;   // 48128
constexpr int AOFF_DEN = AOFF_PL + TLQ * PSTR * 2;  // 55296
constexpr int SMEM_ATTN = AOFF_DEN + TLQ * 2 * 4;   // 55808

__global__ __launch_bounds__(256, 3) void attn_mma(
    const __nv_bfloat16* __restrict__ qh, const __nv_bfloat16* __restrict__ ql,
    const __nv_bfloat16* __restrict__ kh, const __nv_bfloat16* __restrict__ kl,
    const __nv_bfloat16* __restrict__ vh, const __nv_bfloat16* __restrict__ vl,
    __nv_bfloat16* __restrict__ oh, __nv_bfloat16* __restrict__ ol)
{
    extern __shared__ char dsm[];
    const uint32_t sb = smem_u32(dsm);

    const int nhid = blockIdx.y;
    const int n    = nhid / HH;
    const int h    = nhid % HH;
    const int l0   = blockIdx.x * TLQ;
    const int tid  = threadIdx.x;
    const int lane = tid & 31;
    const int wid  = tid >> 5;
    const int mt   = wid & 3;
    const int nhf  = wid >> 2;
    const int grp  = lane >> 2;
    const int tig  = lane & 3;

    // --- stage Q
    {
        const int row = tid >> 2, ch = tid & 3;
        const size_t src = ((size_t)(l0 + row) * NB + n) * EE + h * HD + ch * 8;
        const uint32_t dst = sb + AOFF_QH + row * (KSTR * 2) + ch * 16;
        cpasync16(dst, qh + src);
        cpasync16(dst + (AOFF_QL - AOFF_QH), ql + src);
    }
    // --- stage K, V
#pragma unroll
    for (int i = 0; i < 2; i++) {
        const int idx = tid + i * 256;
        if (idx < KR * 4) {
            const int row = idx >> 2, ch = idx & 3;
            const int gl = l0 - 32 + row;
            const uint32_t dk = sb + AOFF_KH + row * (KSTR * 2) + ch * 16;
            const uint32_t dv = sb + AOFF_VH + row * (KSTR * 2) + ch * 16;
            if (gl >= 0) {
                const size_t src = ((size_t)gl * NB + n) * EE + h * HD + ch * 8;
                cpasync16(dk, kh + src);
                cpasync16(dk + (AOFF_KL - AOFF_KH), kl + src);
                cpasync16(dv, vh + src);
                cpasync16(dv + (AOFF_VL - AOFF_VH), vl + src);
            } else {
                const uint4 z4 = make_uint4(0, 0, 0, 0);
                const int bo = row * (KSTR * 2) + ch * 16;
                *reinterpret_cast<uint4*>(dsm + AOFF_KH + bo) = z4;
                *reinterpret_cast<uint4*>(dsm + AOFF_KL + bo) = z4;
                *reinterpret_cast<uint4*>(dsm + AOFF_VH + bo) = z4;
                *reinterpret_cast<uint4*>(dsm + AOFF_VL + bo) = z4;
            }
        }
    }
    asm volatile("cp.async.commit_group;");
    asm volatile("cp.async.wait_group 0;");
    __syncthreads();

    const int a_row_l = lane & 15;
    const int a_col_l = (lane >> 4) * 8;
    const int b_row_l = (lane & 7) + ((lane >> 4) << 3);
    const int b_col_l = ((lane >> 3) & 1) * 8;

    // --- banded score GEMM: rows [16mt,+16), band cols 48
    float scacc[3][4];
#pragma unroll
    for (int t = 0; t < 3; t++)
#pragma unroll
        for (int i = 0; i < 4; i++) scacc[t][i] = 0.0f;

#pragma unroll
    for (int ks = 0; ks < 2; ks++) {
        const int kb = ks * 16;
        uint32_t qa[4], qb[4];
        const uint32_t aoff = (mt * 16 + a_row_l) * (KSTR * 2) + (kb + a_col_l) * 2;
        ldmx4(qa, sb + AOFF_QH + aoff);
        ldmx4(qb, sb + AOFF_QL + aoff);
        // F0: key rows band [nhf*16, +16); F1: key rows band [32, +16)
        const uint32_t b0off = (mt * 16 + nhf * 16 + b_row_l) * (KSTR * 2) + (kb + b_col_l) * 2;
        const uint32_t b1off = (mt * 16 + 32 + b_row_l) * (KSTR * 2) + (kb + b_col_l) * 2;
        uint32_t k0h[4], k0l[4], k1h[4], k1l[4];
        ldmx4(k0h, sb + AOFF_KH + b0off);
        ldmx4(k0l, sb + AOFF_KL + b0off);
        ldmx4(k1h, sb + AOFF_KH + b1off);
        ldmx4(k1l, sb + AOFF_KL + b1off);
#pragma unroll
        for (int j = 0; j < 2; j++) {
            mma_bf16(scacc[j], qa[0], qa[1], qa[2], qa[3], k0h[2 * j], k0h[2 * j + 1]);
            mma_bf16(scacc[j], qa[0], qa[1], qa[2], qa[3], k0l[2 * j], k0l[2 * j + 1]);
            mma_bf16(scacc[j], qb[0], qb[1], qb[2], qb[3], k0h[2 * j], k0h[2 * j + 1]);
        }
        mma_bf16(scacc[2], qa[0], qa[1], qa[2], qa[3], k1h[2 * nhf], k1h[2 * nhf + 1]);
        mma_bf16(scacc[2], qa[0], qa[1], qa[2], qa[3], k1l[2 * nhf], k1l[2 * nhf + 1]);
        mma_bf16(scacc[2], qb[0], qb[1], qb[2], qb[3], k1h[2 * nhf], k1h[2 * nhf + 1]);
    }

    // --- mask + exp + banded P store + denominator partials
    const int rr0 = grp;            // band-local row
    const int rr1 = grp + 8;
    const int prow0 = mt * 16 + grp;
    const int prow1 = prow0 + 8;
    float sA = 0.0f, sB = 0.0f;
#pragma unroll
    for (int t = 0; t < 3; t++) {
        const int cc0 = ((t < 2) ? (nhf * 16 + t * 8) : (32 + nhf * 8)) + 2 * tig;
        const int cc1 = cc0 + 1;
        const int gbase = l0 + mt * 16;   // gl = gbase - 32 + cc
        const float m00 = (cc0 >= rr0 && cc0 <= rr0 + 32 && gbase + cc0 >= 32) ? 0.0f : NEG;
        const float m01 = (cc1 >= rr0 && cc1 <= rr0 + 32 && gbase + cc1 >= 32) ? 0.0f : NEG;
        const float m10 = (cc0 >= rr1 && cc0 <= rr1 + 32 && gbase + cc0 >= 32) ? 0.0f : NEG;
        const float m11 = (cc1 >= rr1 && cc1 <= rr1 + 32 && gbase + cc1 >= 32) ? 0.0f : NEG;
        const float e00 = __expf(scacc[t][0] + m00);
        const float e01 = __expf(scacc[t][1] + m01);
        const float e10 = __expf(scacc[t][2] + m10);
        const float e11 = __expf(scacc[t][3] + m11);
        sA += e00 + e01;
        sB += e10 + e11;
        uint32_t hi0, lo0, hi1, lo1;
        pack2(e00, e01, hi0, lo0);
        pack2(e10, e11, hi1, lo1);
        const int bo0 = (prow0 * PSTR + cc0) * 2;
        const int bo1 = (prow1 * PSTR + cc0) * 2;
        *reinterpret_cast<uint32_t*>(dsm + AOFF_PH + bo0) = hi0;
        *reinterpret_cast<uint32_t*>(dsm + AOFF_PL + bo0) = lo0;
        *reinterpret_cast<uint32_t*>(dsm + AOFF_PH + bo1) = hi1;
        *reinterpret_cast<uint32_t*>(dsm + AOFF_PL + bo1) = lo1;
    }
    sA += __shfl_xor_sync(0xFFFFFFFFu, sA, 1);
    sA += __shfl_xor_sync(0xFFFFFFFFu, sA, 2);
    sB += __shfl_xor_sync(0xFFFFFFFFu, sB, 1);
    sB += __shfl_xor_sync(0xFFFFFFFFu, sB, 2);
    if (tig == 0) {
        *reinterpret_cast<float*>(dsm + AOFF_DEN + (prow0 * 2 + nhf) * 4) = sA;
        *reinterpret_cast<float*>(dsm + AOFF_DEN + (prow1 * 2 + nhf) * 4) = sB;
    }
    __syncthreads();

    // --- banded output GEMM: O rows [16mt,+16), dims [nhf*16,+16),
    //     K over the 48-deep band (V rows [16mt, 16mt+48))
    float oacc[2][4];
#pragma unroll
    for (int j = 0; j < 2; j++)
#pragma unroll
        for (int i = 0; i < 4; i++) oacc[j][i] = 0.0f;

#pragma unroll
    for (int ks = 0; ks < 3; ks++) {
        const int kb = ks * 16;   // band-local k offset
        uint32_t pa[4], pb[4];
        const uint32_t aoff = (mt * 16 + a_row_l) * (PSTR * 2) + (kb + a_col_l) * 2;
        ldmx4(pa, sb + AOFF_PH + aoff);
        ldmx4(pb, sb + AOFF_PL + aoff);
        const uint32_t voff =
            (mt * 16 + kb + a_row_l) * (KSTR * 2) + nhf * 32 + (lane >> 4) * 16;
        uint32_t vth[4], vtl[4];
        ldmx4t(vth, sb + AOFF_VH + voff);
        ldmx4t(vtl, sb + AOFF_VL + voff);
#pragma unroll
        for (int j = 0; j < 2; j++) {
            mma_bf16(oacc[j], pa[0], pa[1], pa[2], pa[3], vth[2 * j], vth[2 * j + 1]);
            mma_bf16(oacc[j], pa[0], pa[1], pa[2], pa[3], vtl[2 * j], vtl[2 * j + 1]);
            mma_bf16(oacc[j], pb[0], pb[1], pb[2], pb[3], vth[2 * j], vth[2 * j + 1]);
        }
    }

    // --- normalize + store
    const float dA = *reinterpret_cast<float*>(dsm + AOFF_DEN + prow0 * 8) +
                     *reinterpret_cast<float*>(dsm + AOFF_DEN + prow0 * 8 + 4);
    const float dB = *reinterpret_cast<float*>(dsm + AOFF_DEN + prow1 * 8) +
                     *reinterpret_cast<float*>(dsm + AOFF_DEN + prow1 * 8 + 4);
    const float invA = 1.0f / dA;
    const float invB = 1.0f / dB;
    const size_t base0 = ((size_t)(l0 + prow0) * NB + n) * EE + h * HD;
    const size_t base1 = ((size_t)(l0 + prow1) * NB + n) * EE + h * HD;
#pragma unroll
    for (int j = 0; j < 2; j++) {
        const int d0 = nhf * 16 + j * 8 + 2 * tig;
        uint32_t hi0, lo0, hi1, lo1;
        pack2(oacc[j][0] * invA, oacc[j][1] * invA, hi0, lo0);
        pack2(oacc[j][2] * invB, oacc[j][3] * invB, hi1, lo1);
        *reinterpret_cast<uint32_t*>(oh + base0 + d0) = hi0;
        *reinterpret_cast<uint32_t*>(ol + base0 + d0) = lo0;
        *reinterpret_cast<uint32_t*>(oh + base1 + d0) = hi1;
        *reinterpret_cast<uint32_t*>(ol + base1 + d0) = lo1;
    }
}

// ---------------------------------------------------------------------------
extern "C" void kernel_launch(void* const* d_in, const int* in_sizes, int n_in,
                              void* d_out, int out_size)
{
    const float* query = (const float*)d_in[0];
    const float* key   = (const float*)d_in[1];
    const float* value = (const float*)d_in[2];
    const float* w_in  = (const float*)d_in[3];
    const float* b_in  = (const float*)d_in[4];
    const float* w_out = (const float*)d_in[5];
    const float* b_out = (const float*)d_in[6];
    float* out = (float*)d_out;

    __nv_bfloat16 *inh = nullptr, *inl = nullptr, *hi = nullptr, *lo = nullptr;
    __nv_bfloat16 *wh = nullptr, *wl = nullptr;
    cudaGetSymbolAddress((void**)&inh, g_inh);
    cudaGetSymbolAddress((void**)&inl, g_inl);
    cudaGetSymbolAddress((void**)&hi,  g_hi);
    cudaGetSymbolAddress((void**)&lo,  g_lo);
    cudaGetSymbolAddress((void**)&wh,  g_wh);
    cudaGetSymbolAddress((void**)&wl,  g_wl);

    __nv_bfloat16 *wih = wh, *wil = wl;
    __nv_bfloat16 *woh = wh + 768 * 256, *wol = wl + 768 * 256;
    __nv_bfloat16 *ohp = hi + 3 * (size_t)LNE, *olp = lo + 3 * (size_t)LNE;

    cudaFuncSetAttribute(gemm_bf16<0>,
        cudaFuncAttributeMaxDynamicSharedMemorySize, SMEM_GEMM);
    cudaFuncSetAttribute(gemm_bf16<1>,
        cudaFuncAttributeMaxDynamicSharedMemorySize, SMEM_GEMM);
    cudaFuncSetAttribute(attn_mma,
        cudaFuncAttributeMaxDynamicSharedMemorySize, SMEM_ATTN);

    cvt_qkv<<<dim3(LNE / 4 / 256, 1, 3), 256>>>(query, key, value, inh, inl);
    cvt_w<<<(W4A + W4B) / 256, 256>>>(w_in, w_out, wh, wl);

    gemm_bf16<1><<<dim3(EE / BN, M / BM, 3), 256, SMEM_GEMM>>>(
        inh, inl, wih, wil, b_in, nullptr, hi, lo);

    attn_mma<<<dim3(LL / TLQ, NB * HH), 256, SMEM_ATTN>>>(
        hi, lo, hi + LNE, lo + LNE, hi + 2 * (size_t)LNE, lo + 2 * (size_t)LNE,
        ohp, olp);

    gemm_bf16<0><<<dim3(EE / BN, M / BM, 1), 256, SMEM_GEMM>>>(
        ohp, olp, woh, wol, b_out, out, nullptr, nullptr);
}